// round 7
// baseline (speedup 1.0000x reference)
#include <cuda_runtime.h>
#include <math.h>

#define BB 128
#define SS 16
#define EE 512
#define RR 1000
#define G3 1536
#define NSCALE 0.04419417382415922f

// ---- device scratch (static, no allocations) ----
__device__ float GI_emb[RR * G3];
__device__ float H1_emb[RR * EE];
__device__ float GHH_emb[RR * G3];
__device__ float g_Krel[RR * EE];
__device__ float g_KW[RR * EE];
__device__ float g_cs[RR];
__device__ float g_AT[EE * EE];
__device__ float g_wvec[EE];
__device__ float g_c0[1];

__device__ float g_gi [BB * SS * G3];
__device__ float g_h1 [BB * SS * EE];
__device__ float g_ghh[BB * SS * G3];

__device__ int   g_src [BB * SS];
__device__ int   g_ord [BB * SS];
__device__ int   g_sel [BB];
__device__ int   g_dslot[BB];
__device__ float g_pscore[BB * SS];

__device__ float g_pair [BB * EE];
__device__ float g_tvec [BB * EE];
__device__ float g_giP  [BB * G3];
__device__ float g_newh1[BB * EE];
__device__ float g_scores[BB * (RR + 1)];
__device__ float g_prob  [BB * (RR + 1) + 16];

typedef unsigned long long ull;
__device__ __forceinline__ ull pack2(float lo, float hi) {
    ull r; asm("mov.b64 %0, {%1, %2};" : "=l"(r) : "f"(lo), "f"(hi)); return r;
}
__device__ __forceinline__ void unpack2(ull v, float& lo, float& hi) {
    asm("mov.b64 {%0, %1}, %2;" : "=f"(lo), "=f"(hi) : "l"(v));
}
#define FMA2(acc, a, b) asm("fma.rn.f32x2 %0, %1, %2, %0;" : "+l"(acc) : "l"(a), "l"(b))

__device__ __forceinline__ float sigmf(float x) { return 1.0f / (1.0f + expf(-x)); }

__device__ __forceinline__ const float* p_gi(int b, int s) {
    int src = g_src[b * SS + s];
    return (src >= 0) ? &GI_emb[(size_t)src * G3] : &g_gi[((size_t)b * SS + s) * G3];
}
__device__ __forceinline__ const float* p_ghh(int b, int s) {
    int src = g_src[b * SS + s];
    return (src >= 0) ? &GHH_emb[(size_t)src * G3] : &g_ghh[((size_t)b * SS + s) * G3];
}
__device__ __forceinline__ const float* p_h1(int b, int s) {
    int src = g_src[b * SS + s];
    return (src >= 0) ? &H1_emb[(size_t)src * EE] : &g_h1[((size_t)b * SS + s) * EE];
}

__global__ void k_init(const int* __restrict__ tokens) {
    int b = blockIdx.x, t = threadIdx.x;
    if (t < SS) {
        g_ord[b * SS + t] = t;
        g_src[b * SS + t] = tokens[b * SS + t];
    }
}

// ============ 64x64 ping-pong GEMM: out[m][n] = dot(A[m,:512], W[n,:512])*scale + bias[n]
// W is N-row-major. flags&1: row m scattered to out + (m*16 + g_dslot[m]) * ldout.
__global__ __launch_bounds__(256) void gemm64(
    const float* __restrict__ A, const float* __restrict__ W,
    const float* __restrict__ bias, float* __restrict__ out,
    int M, int N, int ldout, int flags, float scale)
{
    __shared__ __align__(16) float As[2][16][68];
    __shared__ __align__(16) float Bs[2][16][68];
    int col0 = blockIdx.x * 64, row0 = blockIdx.y * 64;
    int t = threadIdx.x, tx = t & 15, ty = t >> 4;
    ull acc[4][2];
#pragma unroll
    for (int i = 0; i < 4; i++) { acc[i][0] = 0ULL; acc[i][1] = 0ULL; }

    int am = t >> 2, akg = t & 3;
    int gmA = row0 + am, gnB = col0 + am;

    float4 ra = (gmA < M) ? *(const float4*)&A[(size_t)gmA * 512 + akg * 4]
                          : make_float4(0.f,0.f,0.f,0.f);
    float4 rb = (gnB < N) ? *(const float4*)&W[(size_t)gnB * 512 + akg * 4]
                          : make_float4(0.f,0.f,0.f,0.f);
    As[0][akg*4+0][am] = ra.x; As[0][akg*4+1][am] = ra.y;
    As[0][akg*4+2][am] = ra.z; As[0][akg*4+3][am] = ra.w;
    Bs[0][akg*4+0][am] = rb.x; Bs[0][akg*4+1][am] = rb.y;
    Bs[0][akg*4+2][am] = rb.z; Bs[0][akg*4+3][am] = rb.w;
    __syncthreads();

    for (int it = 0; it < 32; it++) {
        int cur = it & 1;
        if (it < 31) {
            int k0 = (it + 1) * 16;
            ra = (gmA < M) ? *(const float4*)&A[(size_t)gmA * 512 + k0 + akg * 4]
                           : make_float4(0.f,0.f,0.f,0.f);
            rb = (gnB < N) ? *(const float4*)&W[(size_t)gnB * 512 + k0 + akg * 4]
                           : make_float4(0.f,0.f,0.f,0.f);
        }
#pragma unroll
        for (int kk = 0; kk < 16; kk++) {
            ull b0 = *(const ull*)&Bs[cur][kk][tx*4];
            ull b1 = *(const ull*)&Bs[cur][kk][tx*4+2];
            float4 a = *(const float4*)&As[cur][kk][ty*4];
            ull a0=pack2(a.x,a.x), a1=pack2(a.y,a.y);
            ull a2=pack2(a.z,a.z), a3=pack2(a.w,a.w);
            FMA2(acc[0][0],a0,b0); FMA2(acc[0][1],a0,b1);
            FMA2(acc[1][0],a1,b0); FMA2(acc[1][1],a1,b1);
            FMA2(acc[2][0],a2,b0); FMA2(acc[2][1],a2,b1);
            FMA2(acc[3][0],a3,b0); FMA2(acc[3][1],a3,b1);
        }
        if (it < 31) {
            int nxt = 1 - cur;
            As[nxt][akg*4+0][am] = ra.x; As[nxt][akg*4+1][am] = ra.y;
            As[nxt][akg*4+2][am] = ra.z; As[nxt][akg*4+3][am] = ra.w;
            Bs[nxt][akg*4+0][am] = rb.x; Bs[nxt][akg*4+1][am] = rb.y;
            Bs[nxt][akg*4+2][am] = rb.z; Bs[nxt][akg*4+3][am] = rb.w;
        }
        __syncthreads();
    }
#pragma unroll
    for (int i = 0; i < 4; i++) {
        int gm = row0 + ty * 4 + i;
        if (gm >= M) continue;
        float* orow = (flags & 1) ? out + ((size_t)gm * SS + g_dslot[gm]) * (size_t)ldout
                                  : out + (size_t)gm * (size_t)ldout;
#pragma unroll
        for (int j = 0; j < 2; j++) {
            float lo, hi;
            unpack2(acc[i][j], lo, hi);
            int c = col0 + tx * 4 + j * 2;
            if (c < N)     orow[c]     = lo * scale + (bias ? bias[c]     : 0.f);
            if (c + 1 < N) orow[c + 1] = hi * scale + (bias ? bias[c + 1] : 0.f);
        }
    }
}

// ============ KW = Krel @ Wq : out[m][n] = sum_k A[m][k] * B[k][n]  (B K-row-major)
__global__ __launch_bounds__(256) void k_gemm_kn(
    const float* __restrict__ A, const float* __restrict__ B,
    float* __restrict__ out, int M, int N, int ldb)
{
    __shared__ __align__(16) float As[16][68];
    __shared__ __align__(16) float Bs[16][68];
    int col0 = blockIdx.x * 64, row0 = blockIdx.y * 64;
    int t = threadIdx.x, tx = t & 15, ty = t >> 4;
    ull acc[4][2];
#pragma unroll
    for (int i = 0; i < 4; i++) { acc[i][0] = 0ULL; acc[i][1] = 0ULL; }

    int am = t >> 2, akg = t & 3;
    int gmA = row0 + am;
    int kkB = t >> 4, ngB = t & 15;

    for (int k0 = 0; k0 < 512; k0 += 16) {
        float4 ra = (gmA < M) ? *(const float4*)&A[(size_t)gmA*512 + k0 + akg*4]
                              : make_float4(0.f,0.f,0.f,0.f);
        float4 rb = *(const float4*)&B[(size_t)(k0 + kkB) * ldb + col0 + ngB * 4];
        As[akg*4+0][am] = ra.x; As[akg*4+1][am] = ra.y;
        As[akg*4+2][am] = ra.z; As[akg*4+3][am] = ra.w;
        Bs[kkB][ngB*4+0] = rb.x; Bs[kkB][ngB*4+1] = rb.y;
        Bs[kkB][ngB*4+2] = rb.z; Bs[kkB][ngB*4+3] = rb.w;
        __syncthreads();
#pragma unroll
        for (int kk = 0; kk < 16; kk++) {
            ull b0 = *(const ull*)&Bs[kk][tx*4];
            ull b1 = *(const ull*)&Bs[kk][tx*4+2];
            float4 a = *(const float4*)&As[kk][ty*4];
            ull a0=pack2(a.x,a.x), a1=pack2(a.y,a.y);
            ull a2=pack2(a.z,a.z), a3=pack2(a.w,a.w);
            FMA2(acc[0][0],a0,b0); FMA2(acc[0][1],a0,b1);
            FMA2(acc[1][0],a1,b0); FMA2(acc[1][1],a1,b1);
            FMA2(acc[2][0],a2,b0); FMA2(acc[2][1],a2,b1);
            FMA2(acc[3][0],a3,b0); FMA2(acc[3][1],a3,b1);
        }
        __syncthreads();
    }
#pragma unroll
    for (int i = 0; i < 4; i++) {
        int gm = row0 + ty * 4 + i;
        if (gm >= M) continue;
#pragma unroll
        for (int j = 0; j < 2; j++) {
            float lo, hi;
            unpack2(acc[i][j], lo, hi);
            int c = col0 + tx * 4 + j * 2;
            if (c < N)     out[(size_t)gm * N + c]     = lo;
            if (c + 1 < N) out[(size_t)gm * N + c + 1] = hi;
        }
    }
}

// ============ AT[m][n] = sum_k Wk[k][m] * Wq[k][n]   (512x512x512, both K-row-major)
__global__ __launch_bounds__(256) void k_gemm_tn(
    const float* __restrict__ P, const float* __restrict__ Q, float* __restrict__ out)
{
    __shared__ __align__(16) float As[16][68];
    __shared__ __align__(16) float Bs[16][68];
    int col0 = blockIdx.x * 64, row0 = blockIdx.y * 64;
    int t = threadIdx.x, tx = t & 15, ty = t >> 4;
    ull acc[4][2];
#pragma unroll
    for (int i = 0; i < 4; i++) { acc[i][0] = 0ULL; acc[i][1] = 0ULL; }
    int kk0 = t >> 4, g = t & 15;

    for (int k0 = 0; k0 < 512; k0 += 16) {
        float4 ra = *(const float4*)&P[(size_t)(k0 + kk0) * 512 + row0 + g * 4];
        float4 rb = *(const float4*)&Q[(size_t)(k0 + kk0) * 512 + col0 + g * 4];
        As[kk0][g*4+0] = ra.x; As[kk0][g*4+1] = ra.y;
        As[kk0][g*4+2] = ra.z; As[kk0][g*4+3] = ra.w;
        Bs[kk0][g*4+0] = rb.x; Bs[kk0][g*4+1] = rb.y;
        Bs[kk0][g*4+2] = rb.z; Bs[kk0][g*4+3] = rb.w;
        __syncthreads();
#pragma unroll
        for (int kk = 0; kk < 16; kk++) {
            ull b0 = *(const ull*)&Bs[kk][tx*4];
            ull b1 = *(const ull*)&Bs[kk][tx*4+2];
            float4 a = *(const float4*)&As[kk][ty*4];
            ull a0=pack2(a.x,a.x), a1=pack2(a.y,a.y);
            ull a2=pack2(a.z,a.z), a3=pack2(a.w,a.w);
            FMA2(acc[0][0],a0,b0); FMA2(acc[0][1],a0,b1);
            FMA2(acc[1][0],a1,b0); FMA2(acc[1][1],a1,b1);
            FMA2(acc[2][0],a2,b0); FMA2(acc[2][1],a2,b1);
            FMA2(acc[3][0],a3,b0); FMA2(acc[3][1],a3,b1);
        }
        __syncthreads();
    }
#pragma unroll
    for (int i = 0; i < 4; i++) {
        int gm = row0 + ty * 4 + i;
#pragma unroll
        for (int j = 0; j < 2; j++) {
            float lo, hi;
            unpack2(acc[i][j], lo, hi);
            int c = col0 + tx * 4 + j * 2;
            out[(size_t)gm * 512 + c]     = lo;
            out[(size_t)gm * 512 + c + 1] = hi;
        }
    }
}

// ============ w[i] = sum_n Wq[n][i]*bk[n] + Wk[n][i]*bq[n];  c0 = bq.bk
__global__ void k_wc(const float* __restrict__ Wq, const float* __restrict__ bq,
                     const float* __restrict__ Wk, const float* __restrict__ bk) {
    __shared__ float red[256];
    int t = threadIdx.x;
    int i = blockIdx.x * 256 + t;
    float acc = 0.f;
    for (int n = 0; n < EE; n++)
        acc += Wq[(size_t)n * EE + i] * bk[n] + Wk[(size_t)n * EE + i] * bq[n];
    g_wvec[i] = acc;
    if (blockIdx.x == 0) {
        float p = 0.f;
        for (int n = t; n < EE; n += 256) p += bq[n] * bk[n];
        red[t] = p; __syncthreads();
        for (int s = 128; s > 0; s >>= 1) { if (t < s) red[t] += red[t + s]; __syncthreads(); }
        if (t == 0) g_c0[0] = red[0];
    }
}

// ============ Per-round fused GEMM from A=g_pair (M=128, K=512), 64x64 ping-pong:
//  xt<16 : scores = (pair@KW^T)*NSCALE + cs   (N=1000, ld=1001)
//  xt<24 : t      =  pair@AT^T + w            (N=512)
//  xt<48 : giP    =  pair@W_ih^T + b_ih       (N=1536)
__global__ __launch_bounds__(256) void k_biggemm(
    const float* __restrict__ W_ih, const float* __restrict__ b_ih)
{
    __shared__ __align__(16) float As[2][16][68];
    __shared__ __align__(16) float Bs[2][16][68];
    int xt = blockIdx.x;
    const float *Wp, *bp; float *op; int N, ld; float scale; int col0;
    if (xt < 16)      { Wp = g_KW;  bp = g_cs;   op = g_scores; N = RR;  ld = RR+1; scale = NSCALE; col0 = xt * 64; }
    else if (xt < 24) { Wp = g_AT;  bp = g_wvec; op = g_tvec;   N = EE;  ld = EE;   scale = 1.f;    col0 = (xt-16) * 64; }
    else              { Wp = W_ih;  bp = b_ih;   op = g_giP;    N = G3;  ld = G3;   scale = 1.f;    col0 = (xt-24) * 64; }
    int row0 = blockIdx.y * 64;
    int t = threadIdx.x, tx = t & 15, ty = t >> 4;
    ull acc[4][2];
#pragma unroll
    for (int i = 0; i < 4; i++) { acc[i][0] = 0ULL; acc[i][1] = 0ULL; }

    int am = t >> 2, akg = t & 3;
    int gmA = row0 + am, gnB = col0 + am;

    float4 ra = *(const float4*)&g_pair[(size_t)gmA * 512 + akg * 4];
    float4 rb = (gnB < N) ? *(const float4*)&Wp[(size_t)gnB * 512 + akg * 4]
                          : make_float4(0.f,0.f,0.f,0.f);
    As[0][akg*4+0][am] = ra.x; As[0][akg*4+1][am] = ra.y;
    As[0][akg*4+2][am] = ra.z; As[0][akg*4+3][am] = ra.w;
    Bs[0][akg*4+0][am] = rb.x; Bs[0][akg*4+1][am] = rb.y;
    Bs[0][akg*4+2][am] = rb.z; Bs[0][akg*4+3][am] = rb.w;
    __syncthreads();

    for (int it = 0; it < 32; it++) {
        int cur = it & 1;
        if (it < 31) {
            int k0 = (it + 1) * 16;
            ra = *(const float4*)&g_pair[(size_t)gmA * 512 + k0 + akg * 4];
            rb = (gnB < N) ? *(const float4*)&Wp[(size_t)gnB * 512 + k0 + akg * 4]
                           : make_float4(0.f,0.f,0.f,0.f);
        }
#pragma unroll
        for (int kk = 0; kk < 16; kk++) {
            ull b0 = *(const ull*)&Bs[cur][kk][tx*4];
            ull b1 = *(const ull*)&Bs[cur][kk][tx*4+2];
            float4 a = *(const float4*)&As[cur][kk][ty*4];
            ull a0=pack2(a.x,a.x), a1=pack2(a.y,a.y);
            ull a2=pack2(a.z,a.z), a3=pack2(a.w,a.w);
            FMA2(acc[0][0],a0,b0); FMA2(acc[0][1],a0,b1);
            FMA2(acc[1][0],a1,b0); FMA2(acc[1][1],a1,b1);
            FMA2(acc[2][0],a2,b0); FMA2(acc[2][1],a2,b1);
            FMA2(acc[3][0],a3,b0); FMA2(acc[3][1],a3,b1);
        }
        if (it < 31) {
            int nxt = 1 - cur;
            As[nxt][akg*4+0][am] = ra.x; As[nxt][akg*4+1][am] = ra.y;
            As[nxt][akg*4+2][am] = ra.z; As[nxt][akg*4+3][am] = ra.w;
            Bs[nxt][akg*4+0][am] = rb.x; Bs[nxt][akg*4+1][am] = rb.y;
            Bs[nxt][akg*4+2][am] = rb.z; Bs[nxt][akg*4+3][am] = rb.w;
        }
        __syncthreads();
    }
#pragma unroll
    for (int i = 0; i < 4; i++) {
        int gm = row0 + ty * 4 + i;
        float* orow = op + (size_t)gm * ld;
#pragma unroll
        for (int j = 0; j < 2; j++) {
            float lo, hi;
            unpack2(acc[i][j], lo, hi);
            int c = col0 + tx * 4 + j * 2;
            if (c < N)     orow[c]     = lo * scale + bp[c];
            if (c + 1 < N) orow[c + 1] = hi * scale + bp[c + 1];
        }
    }
}

// ============ giMix: gi = prob[:1000] @ GI_emb + p_pair * giP  (64x64 ping-pong)
__global__ __launch_bounds__(256) void k_giMix() {
    __shared__ __align__(16) float As[2][16][68];
    __shared__ __align__(16) float Bs[2][16][68];
    int col0 = blockIdx.x * 64, row0 = blockIdx.y * 64;
    int t = threadIdx.x, tx = t & 15, ty = t >> 4;
    ull acc[4][2];
#pragma unroll
    for (int i = 0; i < 4; i++) { acc[i][0] = 0ULL; acc[i][1] = 0ULL; }

    int am = t >> 2, akg = t & 3;
    int gmA = row0 + am;
    int kkB = t >> 4, ngB = t & 15;
    const float* prow = &g_prob[(size_t)gmA * (RR + 1)];

    float pa[4];
#pragma unroll
    for (int u = 0; u < 4; u++) { int k = akg * 4 + u; pa[u] = (k < RR) ? prow[k] : 0.f; }
    float4 rb = (kkB < RR) ? *(const float4*)&GI_emb[(size_t)kkB * G3 + col0 + ngB * 4]
                           : make_float4(0.f,0.f,0.f,0.f);
    As[0][akg*4+0][am] = pa[0]; As[0][akg*4+1][am] = pa[1];
    As[0][akg*4+2][am] = pa[2]; As[0][akg*4+3][am] = pa[3];
    Bs[0][kkB][ngB*4+0] = rb.x; Bs[0][kkB][ngB*4+1] = rb.y;
    Bs[0][kkB][ngB*4+2] = rb.z; Bs[0][kkB][ngB*4+3] = rb.w;
    __syncthreads();

    const int NIT = 63;  // 63*16 = 1008 >= 1000
    for (int it = 0; it < NIT; it++) {
        int cur = it & 1;
        if (it < NIT - 1) {
            int k0 = (it + 1) * 16;
#pragma unroll
            for (int u = 0; u < 4; u++) { int k = k0 + akg * 4 + u; pa[u] = (k < RR) ? prow[k] : 0.f; }
            int kb = k0 + kkB;
            rb = (kb < RR) ? *(const float4*)&GI_emb[(size_t)kb * G3 + col0 + ngB * 4]
                           : make_float4(0.f,0.f,0.f,0.f);
        }
#pragma unroll
        for (int kk = 0; kk < 16; kk++) {
            ull b0 = *(const ull*)&Bs[cur][kk][tx*4];
            ull b1 = *(const ull*)&Bs[cur][kk][tx*4+2];
            float4 a = *(const float4*)&As[cur][kk][ty*4];
            ull a0=pack2(a.x,a.x), a1=pack2(a.y,a.y);
            ull a2=pack2(a.z,a.z), a3=pack2(a.w,a.w);
            FMA2(acc[0][0],a0,b0); FMA2(acc[0][1],a0,b1);
            FMA2(acc[1][0],a1,b0); FMA2(acc[1][1],a1,b1);
            FMA2(acc[2][0],a2,b0); FMA2(acc[2][1],a2,b1);
            FMA2(acc[3][0],a3,b0); FMA2(acc[3][1],a3,b1);
        }
        if (it < NIT - 1) {
            int nxt = 1 - cur;
            As[nxt][akg*4+0][am] = pa[0]; As[nxt][akg*4+1][am] = pa[1];
            As[nxt][akg*4+2][am] = pa[2]; As[nxt][akg*4+3][am] = pa[3];
            Bs[nxt][kkB][ngB*4+0] = rb.x; Bs[nxt][kkB][ngB*4+1] = rb.y;
            Bs[nxt][kkB][ngB*4+2] = rb.z; Bs[nxt][kkB][ngB*4+3] = rb.w;
        }
        __syncthreads();
    }
#pragma unroll
    for (int i = 0; i < 4; i++) {
        int gm = row0 + ty * 4 + i;
        float pp = g_prob[(size_t)gm * (RR + 1) + RR];
        int slot = g_dslot[gm];
        float* orow = &g_gi[((size_t)gm * SS + slot) * G3];
        const float* gp = &g_giP[(size_t)gm * G3];
#pragma unroll
        for (int j = 0; j < 2; j++) {
            float lo, hi;
            unpack2(acc[i][j], lo, hi);
            int c = col0 + tx * 4 + j * 2;
            orow[c]     = lo + pp * gp[c];
            orow[c + 1] = hi + pp * gp[c + 1];
        }
    }
}

__global__ void k_h1emb(const float* __restrict__ b_hh) {
    int tk = blockIdx.x;
    const float* gi = &GI_emb[(size_t)tk * G3];
    for (int e = threadIdx.x; e < EE; e += blockDim.x) {
        float r = sigmf(gi[e] + b_hh[e]);
        float z = sigmf(gi[EE + e] + b_hh[EE + e]);
        float n = tanhf(gi[2 * EE + e] + r * b_hh[2 * EE + e]);
        H1_emb[(size_t)tk * EE + e] = (1.f - z) * n;
    }
}

__global__ void k_h1inc(const float* __restrict__ b_hh) {
    int b = blockIdx.x;
    int d = g_dslot[b];
    const float* gi = &g_gi[((size_t)b * SS + d) * G3];
    for (int e = threadIdx.x; e < EE; e += blockDim.x) {
        float r = sigmf(gi[e] + b_hh[e]);
        float z = sigmf(gi[EE + e] + b_hh[EE + e]);
        float n = tanhf(gi[2 * EE + e] + r * b_hh[2 * EE + e]);
        float h = (1.f - z) * n;
        g_h1[((size_t)b * SS + d) * EE + e] = h;
        g_newh1[(size_t)b * EE + e] = h;
    }
}

__global__ void k_cinit(const float* __restrict__ bq) {
    int r = blockIdx.x * 8 + (threadIdx.x >> 5);
    int lane = threadIdx.x & 31;
    if (r >= RR) return;
    float s = 0.f;
    for (int e = lane; e < EE; e += 32) s += bq[e] * g_Krel[(size_t)r * EE + e];
#pragma unroll
    for (int off = 16; off > 0; off >>= 1) s += __shfl_down_sync(0xffffffffu, s, off);
    if (lane == 0) g_cs[r] = NSCALE * s;
}

__device__ __forceinline__ float pair_elem(const float* gi, const float* gh,
                                           const float* h1, int e) {
    float r = sigmf(gi[e] + gh[e]);
    float z = sigmf(gi[EE + e] + gh[EE + e]);
    float n = tanhf(gi[2 * EE + e] + r * gh[2 * EE + e]);
    return (1.f - z) * n + z * h1[e];
}

__global__ void k_pairsel(const float* __restrict__ wfc, const float* __restrict__ bfc,
                          int npairs, int zloss, float* __restrict__ loss_out, int first) {
    int b = blockIdx.x, t = threadIdx.x;
    int w = t >> 5, lane = t & 31;
    __shared__ int sord[SS];
    __shared__ float sps[SS];
    __shared__ int sbestj;
    if (t < SS) {
        sord[t] = g_ord[b * SS + t];
        sps[t]  = g_pscore[b * SS + t];
    }
    int prev_sel = g_sel[b];
    __syncthreads();

    int j0 = -1, j1 = -1;
    if (first) {
        j0 = w;
        j1 = w + 8;
        if (j0 >= npairs) j0 = -1;
        if (j1 >= npairs) j1 = -1;
    } else {
        int cnt = 0, jj[2];
        if (prev_sel - 1 >= 0 && prev_sel - 1 < npairs) jj[cnt++] = prev_sel - 1;
        if (prev_sel >= 0 && prev_sel < npairs)         jj[cnt++] = prev_sel;
        if (w < cnt) j0 = jj[w];
    }
#pragma unroll
    for (int rep = 0; rep < 2; rep++) {
        int j = (rep == 0) ? j0 : j1;
        if (j >= 0) {
            const float* gi = p_gi(b, sord[j + 1]);
            const float* gh = p_ghh(b, sord[j]);
            const float* h1 = p_h1(b, sord[j]);
            float s = 0.f;
            for (int e = lane; e < EE; e += 32)
                s += pair_elem(gi, gh, h1, e) * wfc[e];
#pragma unroll
            for (int off = 16; off > 0; off >>= 1)
                s += __shfl_down_sync(0xffffffffu, s, off);
            if (lane == 0) {
                float sc = sigmf(s + bfc[0]);
                sps[j] = sc;
                g_pscore[b * SS + j] = sc;
            }
        }
    }
    __syncthreads();

    if (t == 0) {
        int bj = 0; float bs = sps[0];
        for (int j = 1; j < npairs; j++)
            if (sps[j] > bs) { bs = sps[j]; bj = j; }
        sbestj = bj;
        g_sel[b] = bj;
        if (zloss >= 0) loss_out[b * SS + zloss] = 0.f;
    }
    __syncthreads();
    int j = sbestj;
    const float* gi = p_gi(b, sord[j + 1]);
    const float* gh = p_ghh(b, sord[j]);
    const float* h1 = p_h1(b, sord[j]);
    for (int e = t; e < EE; e += 256)
        g_pair[(size_t)b * EE + e] = pair_elem(gi, gh, h1, e);
}

__device__ __forceinline__ float bsum(float v, float* red, int t) {
    red[t] = v; __syncthreads();
    for (int s = 128; s > 0; s >>= 1) { if (t < s) red[t] += red[t + s]; __syncthreads(); }
    return red[0];
}
__device__ __forceinline__ float bmax(float v, float* red, int t) {
    red[t] = v; __syncthreads();
    for (int s = 128; s > 0; s >>= 1) { if (t < s) red[t] = fmaxf(red[t], red[t + s]); __syncthreads(); }
    return red[0];
}

__global__ void k_softmax(int lossidx, int L, int do_book,
                          float* __restrict__ loss_out, float* __restrict__ scores_out) {
    int b = blockIdx.x, t = threadIdx.x;
    __shared__ float red[256];
    const float* tv = &g_tvec[(size_t)b * EE];
    const float* pp = &g_pair[(size_t)b * EE];
    const float* sc = &g_scores[(size_t)b * (RR + 1)];

    float part = 0.f;
    for (int e = t; e < EE; e += 256) part += tv[e] * pp[e];
    float c1000 = (bsum(part, red, t) + g_c0[0]) * NSCALE;
    __syncthreads();

    float m = -3.4e38f;
    for (int k = t; k <= RR; k += 256)
        m = fmaxf(m, (k < RR) ? sc[k] : c1000);
    m = bmax(m, red, t);
    __syncthreads();

    float se = 0.f, sv = 0.f;
    for (int k = t; k <= RR; k += 256) {
        float v = ((k < RR) ? sc[k] : c1000) - m;
        float ev = expf(v);
        se += ev; sv += ev * v;
    }
    float Z = bsum(se, red, t);
    __syncthreads();
    float S2 = bsum(sv, red, t);
    if (t == 0) loss_out[b * SS + lossidx] = logf(Z) - S2 / Z;

    float* pr = &g_prob[(size_t)b * (RR + 1)];
    for (int k = t; k <= RR; k += 256) {
        float raw = (k < RR) ? sc[k] : c1000;
        pr[k] = expf(raw - m) / Z;
        if (scores_out) scores_out[(size_t)b * (RR + 1) + k] = raw;
    }
    if (t == 0 && do_book) {
        int sel = g_sel[b];
        int* ord = &g_ord[b * SS];
        float* ps = &g_pscore[b * SS];
        int slot = ord[sel];
        g_dslot[b] = slot;
        g_src[b * SS + slot] = -1;
        for (int i = sel + 1; i < L - 1; i++) { ord[i] = ord[i + 1]; ps[i] = ps[i + 1]; }
    }
}

// ---------------- host ----------------
extern "C" void kernel_launch(void* const* d_in, const int* in_sizes, int n_in,
                              void* d_out, int out_size) {
    const int*   tokens = (const int*)  d_in[0];
    const float* emb    = (const float*)d_in[1];
    const float* W_ih   = (const float*)d_in[2];
    const float* W_hh   = (const float*)d_in[3];
    const float* b_ih   = (const float*)d_in[4];
    const float* b_hh   = (const float*)d_in[5];
    const float* w_fc   = (const float*)d_in[6];
    const float* b_fc   = (const float*)d_in[7];
    const float* Wq     = (const float*)d_in[8];
    const float* bq     = (const float*)d_in[9];
    const float* Wk     = (const float*)d_in[10];
    const float* bk     = (const float*)d_in[11];

    float* out_scores = (float*)d_out;                         // 128 x 1001
    float* out_loss   = (float*)d_out + (size_t)BB * (RR + 1); // 128 x 16

    float *GI, *H1, *GHH, *Krel, *KW, *AT, *newh1, *ghh;
    cudaGetSymbolAddress((void**)&GI, GI_emb);
    cudaGetSymbolAddress((void**)&H1, H1_emb);
    cudaGetSymbolAddress((void**)&GHH, GHH_emb);
    cudaGetSymbolAddress((void**)&Krel, g_Krel);
    cudaGetSymbolAddress((void**)&KW, g_KW);
    cudaGetSymbolAddress((void**)&AT, g_AT);
    cudaGetSymbolAddress((void**)&newh1, g_newh1);
    cudaGetSymbolAddress((void**)&ghh, g_ghh);

    // ---- init (once per call) ----
    k_init<<<BB, 32>>>(tokens);
    gemm64<<<dim3(24, 16), 256>>>(emb, W_ih, b_ih, GI, RR, G3, G3, 0, 1.f);
    k_h1emb<<<RR, 256>>>(b_hh);
    gemm64<<<dim3(24, 16), 256>>>(H1, W_hh, b_hh, GHH, RR, G3, G3, 0, 1.f);
    gemm64<<<dim3(8, 16), 256>>>(emb, Wk, bk, Krel, RR, EE, EE, 0, 1.f);
    k_gemm_kn<<<dim3(8, 16), 256>>>(Krel, Wq, KW, RR, EE, EE);
    k_cinit<<<125, 256>>>(bq);
    k_gemm_tn<<<dim3(8, 8), 256>>>(Wk, Wq, AT);
    k_wc<<<2, 256>>>(Wq, bq, Wk, bk);

    // ---- 14 merge rounds ----
    for (int i = 0; i < 14; i++) {
        int L = SS - i;
        k_pairsel<<<BB, 256>>>(w_fc, b_fc, L - 1, -1, out_loss, i == 0);
        k_biggemm<<<dim3(48, 2), 256>>>(W_ih, b_ih);
        k_softmax<<<BB, 256>>>(i, L, 1, out_loss, NULL);
        k_giMix<<<dim3(24, 2), 256>>>();
        k_h1inc<<<BB, 256>>>(b_hh);
        gemm64<<<dim3(24, 2), 256>>>(newh1, W_hh, b_hh, ghh, BB, G3, G3, 1, 1.f);
    }
    // ---- final round (L=2) + output attention ----
    k_pairsel<<<BB, 256>>>(w_fc, b_fc, 1, 14, out_loss, 0);
    k_biggemm<<<dim3(24, 2), 256>>>(W_ih, b_ih);
    k_softmax<<<BB, 256>>>(15, 0, 0, out_loss, out_scores);
}

// round 8
// speedup vs baseline: 1.0052x; 1.0052x over previous
#include <cuda_runtime.h>
#include <math.h>

#define BB 128
#define SS 16
#define EE 512
#define RR 1000
#define G3 1536
#define NSCALE 0.04419417382415922f
#define NBLK 148

// ---- device scratch (static, no allocations) ----
__device__ float GI_emb[RR * G3];
__device__ float H1_emb[RR * EE];
__device__ float GHH_emb[RR * G3];
__device__ float g_Krel[RR * EE];
__device__ float g_KW[RR * EE];
__device__ float g_cs[RR];
__device__ float g_AT[EE * EE];
__device__ float g_wvec[EE];
__device__ float g_c0[1];

__device__ float g_gi [BB * SS * G3];
__device__ float g_h1 [BB * SS * EE];
__device__ float g_ghh[BB * SS * G3];

__device__ int   g_src [BB * SS];
__device__ int   g_ord [BB * SS];
__device__ int   g_sel [BB];
__device__ int   g_dslot[BB];
__device__ float g_pscore[BB * SS];

__device__ float g_pair [BB * EE];
__device__ float g_tvec [BB * EE];
__device__ float g_giP  [BB * G3];
__device__ float g_newh1[BB * EE];
__device__ float g_scores[BB * (RR + 1)];
__device__ float g_prob  [BB * (RR + 1) + 16];

__device__ unsigned g_cnt = 0;
__device__ unsigned g_gen = 0;

typedef unsigned long long ull;
__device__ __forceinline__ ull pack2(float lo, float hi) {
    ull r; asm("mov.b64 %0, {%1, %2};" : "=l"(r) : "f"(lo), "f"(hi)); return r;
}
__device__ __forceinline__ void unpack2(ull v, float& lo, float& hi) {
    asm("mov.b64 {%0, %1}, %2;" : "=f"(lo), "=f"(hi) : "l"(v));
}
#define FMA2(acc, a, b) asm("fma.rn.f32x2 %0, %1, %2, %0;" : "+l"(acc) : "l"(a), "l"(b))

__device__ __forceinline__ float sigmf(float x) { return 1.0f / (1.0f + expf(-x)); }

// ---- software grid barrier (all NBLK blocks co-resident: grid <= SM count) ----
__device__ __forceinline__ void gsync() {
    __syncthreads();
    if (threadIdx.x == 0) {
        __threadfence();
        unsigned gen = *((volatile unsigned*)&g_gen);
        if (atomicAdd(&g_cnt, 1u) == NBLK - 1) {
            *((volatile unsigned*)&g_cnt) = 0;
            __threadfence();
            atomicExch(&g_gen, gen + 1);
        } else {
            while (*((volatile unsigned*)&g_gen) == gen) { __nanosleep(64); }
        }
        __threadfence();
    }
    __syncthreads();
}

__device__ __forceinline__ const float* p_gi(int b, int s) {
    int src = g_src[b * SS + s];
    return (src >= 0) ? &GI_emb[(size_t)src * G3] : &g_gi[((size_t)b * SS + s) * G3];
}
__device__ __forceinline__ const float* p_ghh(int b, int s) {
    int src = g_src[b * SS + s];
    return (src >= 0) ? &GHH_emb[(size_t)src * G3] : &g_ghh[((size_t)b * SS + s) * G3];
}
__device__ __forceinline__ const float* p_h1(int b, int s) {
    int src = g_src[b * SS + s];
    return (src >= 0) ? &H1_emb[(size_t)src * EE] : &g_h1[((size_t)b * SS + s) * EE];
}

__global__ void k_init(const int* __restrict__ tokens) {
    int b = blockIdx.x, t = threadIdx.x;
    if (t < SS) {
        g_ord[b * SS + t] = t;
        g_src[b * SS + t] = tokens[b * SS + t];
    }
}

// ============ init-time 64x64 ping-pong GEMM (tables): out = A@W^T*scale + bias
__global__ __launch_bounds__(256) void gemm64(
    const float* __restrict__ A, const float* __restrict__ W,
    const float* __restrict__ bias, float* __restrict__ out,
    int M, int N, int ldout, float scale)
{
    __shared__ __align__(16) float As[2][16][68];
    __shared__ __align__(16) float Bs[2][16][68];
    int col0 = blockIdx.x * 64, row0 = blockIdx.y * 64;
    int t = threadIdx.x, tx = t & 15, ty = t >> 4;
    ull acc[4][2];
#pragma unroll
    for (int i = 0; i < 4; i++) { acc[i][0] = 0ULL; acc[i][1] = 0ULL; }

    int am = t >> 2, akg = t & 3;
    int gmA = row0 + am, gnB = col0 + am;

    float4 ra = (gmA < M) ? *(const float4*)&A[(size_t)gmA * 512 + akg * 4]
                          : make_float4(0.f,0.f,0.f,0.f);
    float4 rb = (gnB < N) ? *(const float4*)&W[(size_t)gnB * 512 + akg * 4]
                          : make_float4(0.f,0.f,0.f,0.f);
    As[0][akg*4+0][am] = ra.x; As[0][akg*4+1][am] = ra.y;
    As[0][akg*4+2][am] = ra.z; As[0][akg*4+3][am] = ra.w;
    Bs[0][akg*4+0][am] = rb.x; Bs[0][akg*4+1][am] = rb.y;
    Bs[0][akg*4+2][am] = rb.z; Bs[0][akg*4+3][am] = rb.w;
    __syncthreads();

    for (int it = 0; it < 32; it++) {
        int cur = it & 1;
        if (it < 31) {
            int k0 = (it + 1) * 16;
            ra = (gmA < M) ? *(const float4*)&A[(size_t)gmA * 512 + k0 + akg * 4]
                           : make_float4(0.f,0.f,0.f,0.f);
            rb = (gnB < N) ? *(const float4*)&W[(size_t)gnB * 512 + k0 + akg * 4]
                           : make_float4(0.f,0.f,0.f,0.f);
        }
#pragma unroll
        for (int kk = 0; kk < 16; kk++) {
            ull b0 = *(const ull*)&Bs[cur][kk][tx*4];
            ull b1 = *(const ull*)&Bs[cur][kk][tx*4+2];
            float4 a = *(const float4*)&As[cur][kk][ty*4];
            ull a0=pack2(a.x,a.x), a1=pack2(a.y,a.y);
            ull a2=pack2(a.z,a.z), a3=pack2(a.w,a.w);
            FMA2(acc[0][0],a0,b0); FMA2(acc[0][1],a0,b1);
            FMA2(acc[1][0],a1,b0); FMA2(acc[1][1],a1,b1);
            FMA2(acc[2][0],a2,b0); FMA2(acc[2][1],a2,b1);
            FMA2(acc[3][0],a3,b0); FMA2(acc[3][1],a3,b1);
        }
        if (it < 31) {
            int nxt = 1 - cur;
            As[nxt][akg*4+0][am] = ra.x; As[nxt][akg*4+1][am] = ra.y;
            As[nxt][akg*4+2][am] = ra.z; As[nxt][akg*4+3][am] = ra.w;
            Bs[nxt][akg*4+0][am] = rb.x; Bs[nxt][akg*4+1][am] = rb.y;
            Bs[nxt][akg*4+2][am] = rb.z; Bs[nxt][akg*4+3][am] = rb.w;
        }
        __syncthreads();
    }
#pragma unroll
    for (int i = 0; i < 4; i++) {
        int gm = row0 + ty * 4 + i;
        if (gm >= M) continue;
        float* orow = out + (size_t)gm * (size_t)ldout;
#pragma unroll
        for (int j = 0; j < 2; j++) {
            float lo, hi;
            unpack2(acc[i][j], lo, hi);
            int c = col0 + tx * 4 + j * 2;
            if (c < N)     orow[c]     = lo * scale + (bias ? bias[c]     : 0.f);
            if (c + 1 < N) orow[c + 1] = hi * scale + (bias ? bias[c + 1] : 0.f);
        }
    }
}

// ============ KW = Krel @ Wq (B K-row-major)
__global__ __launch_bounds__(256) void k_gemm_kn(
    const float* __restrict__ A, const float* __restrict__ B,
    float* __restrict__ out, int M, int N, int ldb)
{
    __shared__ __align__(16) float As[16][68];
    __shared__ __align__(16) float Bs[16][68];
    int col0 = blockIdx.x * 64, row0 = blockIdx.y * 64;
    int t = threadIdx.x, tx = t & 15, ty = t >> 4;
    ull acc[4][2];
#pragma unroll
    for (int i = 0; i < 4; i++) { acc[i][0] = 0ULL; acc[i][1] = 0ULL; }

    int am = t >> 2, akg = t & 3;
    int gmA = row0 + am;
    int kkB = t >> 4, ngB = t & 15;

    for (int k0 = 0; k0 < 512; k0 += 16) {
        float4 ra = (gmA < M) ? *(const float4*)&A[(size_t)gmA*512 + k0 + akg*4]
                              : make_float4(0.f,0.f,0.f,0.f);
        float4 rb = *(const float4*)&B[(size_t)(k0 + kkB) * ldb + col0 + ngB * 4];
        As[akg*4+0][am] = ra.x; As[akg*4+1][am] = ra.y;
        As[akg*4+2][am] = ra.z; As[akg*4+3][am] = ra.w;
        Bs[kkB][ngB*4+0] = rb.x; Bs[kkB][ngB*4+1] = rb.y;
        Bs[kkB][ngB*4+2] = rb.z; Bs[kkB][ngB*4+3] = rb.w;
        __syncthreads();
#pragma unroll
        for (int kk = 0; kk < 16; kk++) {
            ull b0 = *(const ull*)&Bs[kk][tx*4];
            ull b1 = *(const ull*)&Bs[kk][tx*4+2];
            float4 a = *(const float4*)&As[kk][ty*4];
            ull a0=pack2(a.x,a.x), a1=pack2(a.y,a.y);
            ull a2=pack2(a.z,a.z), a3=pack2(a.w,a.w);
            FMA2(acc[0][0],a0,b0); FMA2(acc[0][1],a0,b1);
            FMA2(acc[1][0],a1,b0); FMA2(acc[1][1],a1,b1);
            FMA2(acc[2][0],a2,b0); FMA2(acc[2][1],a2,b1);
            FMA2(acc[3][0],a3,b0); FMA2(acc[3][1],a3,b1);
        }
        __syncthreads();
    }
#pragma unroll
    for (int i = 0; i < 4; i++) {
        int gm = row0 + ty * 4 + i;
        if (gm >= M) continue;
#pragma unroll
        for (int j = 0; j < 2; j++) {
            float lo, hi;
            unpack2(acc[i][j], lo, hi);
            int c = col0 + tx * 4 + j * 2;
            if (c < N)     out[(size_t)gm * N + c]     = lo;
            if (c + 1 < N) out[(size_t)gm * N + c + 1] = hi;
        }
    }
}

// ============ AT[m][n] = sum_k Wk[k][m] * Wq[k][n]
__global__ __launch_bounds__(256) void k_gemm_tn(
    const float* __restrict__ P, const float* __restrict__ Q, float* __restrict__ out)
{
    __shared__ __align__(16) float As[16][68];
    __shared__ __align__(16) float Bs[16][68];
    int col0 = blockIdx.x * 64, row0 = blockIdx.y * 64;
    int t = threadIdx.x, tx = t & 15, ty = t >> 4;
    ull acc[4][2];
#pragma unroll
    for (int i = 0; i < 4; i++) { acc[i][0] = 0ULL; acc[i][1] = 0ULL; }
    int kk0 = t >> 4, g = t & 15;

    for (int k0 = 0; k0 < 512; k0 += 16) {
        float4 ra = *(const float4*)&P[(size_t)(k0 + kk0) * 512 + row0 + g * 4];
        float4 rb = *(const float4*)&Q[(size_t)(k0 + kk0) * 512 + col0 + g * 4];
        As[kk0][g*4+0] = ra.x; As[kk0][g*4+1] = ra.y;
        As[kk0][g*4+2] = ra.z; As[kk0][g*4+3] = ra.w;
        Bs[kk0][g*4+0] = rb.x; Bs[kk0][g*4+1] = rb.y;
        Bs[kk0][g*4+2] = rb.z; Bs[kk0][g*4+3] = rb.w;
        __syncthreads();
#pragma unroll
        for (int kk = 0; kk < 16; kk++) {
            ull b0 = *(const ull*)&Bs[kk][tx*4];
            ull b1 = *(const ull*)&Bs[kk][tx*4+2];
            float4 a = *(const float4*)&As[kk][ty*4];
            ull a0=pack2(a.x,a.x), a1=pack2(a.y,a.y);
            ull a2=pack2(a.z,a.z), a3=pack2(a.w,a.w);
            FMA2(acc[0][0],a0,b0); FMA2(acc[0][1],a0,b1);
            FMA2(acc[1][0],a1,b0); FMA2(acc[1][1],a1,b1);
            FMA2(acc[2][0],a2,b0); FMA2(acc[2][1],a2,b1);
            FMA2(acc[3][0],a3,b0); FMA2(acc[3][1],a3,b1);
        }
        __syncthreads();
    }
#pragma unroll
    for (int i = 0; i < 4; i++) {
        int gm = row0 + ty * 4 + i;
#pragma unroll
        for (int j = 0; j < 2; j++) {
            float lo, hi;
            unpack2(acc[i][j], lo, hi);
            int c = col0 + tx * 4 + j * 2;
            out[(size_t)gm * 512 + c]     = lo;
            out[(size_t)gm * 512 + c + 1] = hi;
        }
    }
}

// ============ w[i] = Wq^T bk + Wk^T bq ;  c0 = bq.bk
__global__ void k_wc(const float* __restrict__ Wq, const float* __restrict__ bq,
                     const float* __restrict__ Wk, const float* __restrict__ bk) {
    __shared__ float red[256];
    int t = threadIdx.x;
    int i = blockIdx.x * 256 + t;
    float acc = 0.f;
    for (int n = 0; n < EE; n++)
        acc += Wq[(size_t)n * EE + i] * bk[n] + Wk[(size_t)n * EE + i] * bq[n];
    g_wvec[i] = acc;
    if (blockIdx.x == 0) {
        float p = 0.f;
        for (int n = t; n < EE; n += 256) p += bq[n] * bk[n];
        red[t] = p; __syncthreads();
        for (int s = 128; s > 0; s >>= 1) { if (t < s) red[t] += red[t + s]; __syncthreads(); }
        if (t == 0) g_c0[0] = red[0];
    }
}

__global__ void k_h1emb(const float* __restrict__ b_hh) {
    int tk = blockIdx.x;
    const float* gi = &GI_emb[(size_t)tk * G3];
    for (int e = threadIdx.x; e < EE; e += blockDim.x) {
        float r = sigmf(gi[e] + b_hh[e]);
        float z = sigmf(gi[EE + e] + b_hh[EE + e]);
        float n = tanhf(gi[2 * EE + e] + r * b_hh[2 * EE + e]);
        H1_emb[(size_t)tk * EE + e] = (1.f - z) * n;
    }
}

__global__ void k_cinit(const float* __restrict__ bq) {
    int r = blockIdx.x * 8 + (threadIdx.x >> 5);
    int lane = threadIdx.x & 31;
    if (r >= RR) return;
    float s = 0.f;
    for (int e = lane; e < EE; e += 32) s += bq[e] * g_Krel[(size_t)r * EE + e];
#pragma unroll
    for (int off = 16; off > 0; off >>= 1) s += __shfl_down_sync(0xffffffffu, s, off);
    if (lane == 0) g_cs[r] = NSCALE * s;
}

// =================== persistent-round device functions ===================

__device__ __forceinline__ float pair_elem(const float* gi, const float* gh,
                                           const float* h1, int e) {
    float r = sigmf(gi[e] + gh[e]);
    float z = sigmf(gi[EE + e] + gh[EE + e]);
    float n = tanhf(gi[2 * EE + e] + r * gh[2 * EE + e]);
    return (1.f - z) * n + z * h1[e];
}

// TM=32/TN=64 GEMM job, K=512, A row-major contiguous (ld 512), W N-row-major.
__device__ void job_gemm(const float* __restrict__ A, const float* __restrict__ Wp,
                         const float* __restrict__ bp, float* __restrict__ op,
                         int N, int ld, float scale, int col0, int row0, int scatter,
                         float* shA, float* shB)
{
    int t = threadIdx.x, tx = t & 15, ty = t >> 4;
    ull a00 = 0ULL, a01 = 0ULL, a10 = 0ULL, a11 = 0ULL;
    int am = t >> 2, akg = t & 3;
    bool hasA = (t < 128);
    int gmA = row0 + am;
    int gnB = col0 + (t >> 2);
    int bkg = t & 3;

    float4 ra = hasA ? *(const float4*)&A[(size_t)gmA * 512 + akg * 4]
                     : make_float4(0.f,0.f,0.f,0.f);
    float4 rb = (gnB < N) ? *(const float4*)&Wp[(size_t)gnB * 512 + bkg * 4]
                          : make_float4(0.f,0.f,0.f,0.f);

    for (int it = 0; it < 32; it++) {
        if (hasA) {
            shA[(akg*4+0)*36+am] = ra.x; shA[(akg*4+1)*36+am] = ra.y;
            shA[(akg*4+2)*36+am] = ra.z; shA[(akg*4+3)*36+am] = ra.w;
        }
        int bn = t >> 2;
        shB[(bkg*4+0)*68+bn] = rb.x; shB[(bkg*4+1)*68+bn] = rb.y;
        shB[(bkg*4+2)*68+bn] = rb.z; shB[(bkg*4+3)*68+bn] = rb.w;
        __syncthreads();
        if (it < 31) {
            int k0 = (it + 1) * 16;
            if (hasA) ra = *(const float4*)&A[(size_t)gmA * 512 + k0 + akg * 4];
            rb = (gnB < N) ? *(const float4*)&Wp[(size_t)gnB * 512 + k0 + bkg * 4]
                           : make_float4(0.f,0.f,0.f,0.f);
        }
#pragma unroll
        for (int kk = 0; kk < 16; kk++) {
            ull b0 = *(const ull*)&shB[kk*68 + tx*4];
            ull b1 = *(const ull*)&shB[kk*68 + tx*4 + 2];
            float2 a = *(const float2*)&shA[kk*36 + ty*2];
            ull q0 = pack2(a.x, a.x), q1 = pack2(a.y, a.y);
            FMA2(a00, q0, b0); FMA2(a01, q0, b1);
            FMA2(a10, q1, b0); FMA2(a11, q1, b1);
        }
        __syncthreads();
    }
#pragma unroll
    for (int i = 0; i < 2; i++) {
        int gm = row0 + ty * 2 + i;
        float* orow = scatter ? op + ((size_t)gm * SS + g_dslot[gm]) * (size_t)ld
                              : op + (size_t)gm * (size_t)ld;
        ull v0 = i ? a10 : a00, v1 = i ? a11 : a01;
#pragma unroll
        for (int j = 0; j < 2; j++) {
            float lo, hi;
            unpack2(j ? v1 : v0, lo, hi);
            int c = col0 + tx * 4 + j * 2;
            if (c < N)     orow[c]     = lo * scale + bp[c];
            if (c + 1 < N) orow[c + 1] = hi * scale + bp[c + 1];
        }
    }
}

// giMix job: gi = prob[:1000] @ GI_emb + p_pair * giP ; output scattered to g_gi.
__device__ void job_gimix(int col0, int row0, float* shA, float* shB)
{
    int t = threadIdx.x, tx = t & 15, ty = t >> 4;
    ull a00 = 0ULL, a01 = 0ULL, a10 = 0ULL, a11 = 0ULL;
    int am = t >> 2, akg = t & 3;
    bool hasA = (t < 128);
    int gmA = row0 + am;
    int kkB = t >> 4, ngB = t & 15;
    const float* prow = &g_prob[(size_t)(hasA ? gmA : 0) * (RR + 1)];

    float pa[4];
#pragma unroll
    for (int u = 0; u < 4; u++) { int k = akg * 4 + u; pa[u] = (hasA && k < RR) ? prow[k] : 0.f; }
    float4 rb = (kkB < RR) ? *(const float4*)&GI_emb[(size_t)kkB * G3 + col0 + ngB * 4]
                           : make_float4(0.f,0.f,0.f,0.f);

    const int NIT = 63;
    for (int it = 0; it < NIT; it++) {
        if (hasA) {
            shA[(akg*4+0)*36+am] = pa[0]; shA[(akg*4+1)*36+am] = pa[1];
            shA[(akg*4+2)*36+am] = pa[2]; shA[(akg*4+3)*36+am] = pa[3];
        }
        shB[kkB*68 + ngB*4 + 0] = rb.x; shB[kkB*68 + ngB*4 + 1] = rb.y;
        shB[kkB*68 + ngB*4 + 2] = rb.z; shB[kkB*68 + ngB*4 + 3] = rb.w;
        __syncthreads();
        if (it < NIT - 1) {
            int k0 = (it + 1) * 16;
#pragma unroll
            for (int u = 0; u < 4; u++) { int k = k0 + akg * 4 + u; pa[u] = (hasA && k < RR) ? prow[k] : 0.f; }
            int kb = k0 + kkB;
            rb = (kb < RR) ? *(const float4*)&GI_emb[(size_t)kb * G3 + col0 + ngB * 4]
                           : make_float4(0.f,0.f,0.f,0.f);
        }
#pragma unroll
        for (int kk = 0; kk < 16; kk++) {
            ull b0 = *(const ull*)&shB[kk*68 + tx*4];
            ull b1 = *(const ull*)&shB[kk*68 + tx*4 + 2];
            float2 a = *(const float2*)&shA[kk*36 + ty*2];
            ull q0 = pack2(a.x, a.x), q1 = pack2(a.y, a.y);
            FMA2(a00, q0, b0); FMA2(a01, q0, b1);
            FMA2(a10, q1, b0); FMA2(a11, q1, b1);
        }
        __syncthreads();
    }
#pragma unroll
    for (int i = 0; i < 2; i++) {
        int gm = row0 + ty * 2 + i;
        float pp = g_prob[(size_t)gm * (RR + 1) + RR];
        int slot = g_dslot[gm];
        float* orow = &g_gi[((size_t)gm * SS + slot) * G3];
        const float* gp = &g_giP[(size_t)gm * G3];
        ull v0 = i ? a10 : a00, v1 = i ? a11 : a01;
#pragma unroll
        for (int j = 0; j < 2; j++) {
            float lo, hi;
            unpack2(j ? v1 : v0, lo, hi);
            int c = col0 + tx * 4 + j * 2;
            orow[c]     = lo + pp * gp[c];
            orow[c + 1] = hi + pp * gp[c + 1];
        }
    }
}

__device__ void ph_pairsel(int b, const float* __restrict__ wfc, const float* __restrict__ bfc,
                           int npairs, int zloss, float* __restrict__ loss_out, int first,
                           int* sord, float* sps, int* smisc)
{
    int t = threadIdx.x;
    int w = t >> 5, lane = t & 31;
    if (t < SS) {
        sord[t] = g_ord[b * SS + t];
        sps[t]  = g_pscore[b * SS + t];
    }
    int prev_sel = g_sel[b];
    __syncthreads();

    int j0 = -1, j1 = -1;
    if (first) {
        j0 = w;  j1 = w + 8;
        if (j0 >= npairs) j0 = -1;
        if (j1 >= npairs) j1 = -1;
    } else {
        int cnt = 0, jj[2];
        if (prev_sel - 1 >= 0 && prev_sel - 1 < npairs) jj[cnt++] = prev_sel - 1;
        if (prev_sel >= 0 && prev_sel < npairs)         jj[cnt++] = prev_sel;
        if (w < cnt) j0 = jj[w];
    }
#pragma unroll
    for (int rep = 0; rep < 2; rep++) {
        int j = (rep == 0) ? j0 : j1;
        if (j >= 0) {
            const float* gi = p_gi(b, sord[j + 1]);
            const float* gh = p_ghh(b, sord[j]);
            const float* h1 = p_h1(b, sord[j]);
            float s = 0.f;
            for (int e = lane; e < EE; e += 32)
                s += pair_elem(gi, gh, h1, e) * wfc[e];
#pragma unroll
            for (int off = 16; off > 0; off >>= 1)
                s += __shfl_down_sync(0xffffffffu, s, off);
            if (lane == 0) {
                float sc = sigmf(s + bfc[0]);
                sps[j] = sc;
                g_pscore[b * SS + j] = sc;
            }
        }
    }
    __syncthreads();

    if (t == 0) {
        int bj = 0; float bs = sps[0];
        for (int j = 1; j < npairs; j++)
            if (sps[j] > bs) { bs = sps[j]; bj = j; }
        smisc[0] = bj;
        g_sel[b] = bj;
        if (zloss >= 0) loss_out[b * SS + zloss] = 0.f;
    }
    __syncthreads();
    int j = smisc[0];
    const float* gi = p_gi(b, sord[j + 1]);
    const float* gh = p_ghh(b, sord[j]);
    const float* h1 = p_h1(b, sord[j]);
    for (int e = t; e < EE; e += 256)
        g_pair[(size_t)b * EE + e] = pair_elem(gi, gh, h1, e);
}

__device__ __forceinline__ float bsum(float v, float* red, int t) {
    red[t] = v; __syncthreads();
    for (int s = 128; s > 0; s >>= 1) { if (t < s) red[t] += red[t + s]; __syncthreads(); }
    return red[0];
}
__device__ __forceinline__ float bmax(float v, float* red, int t) {
    red[t] = v; __syncthreads();
    for (int s = 128; s > 0; s >>= 1) { if (t < s) red[t] = fmaxf(red[t], red[t + s]); __syncthreads(); }
    return red[0];
}

__device__ void ph_softmax(int b, int lossidx, int L, int do_book,
                           float* __restrict__ loss_out, float* __restrict__ scores_out,
                           float* red)
{
    int t = threadIdx.x;
    const float* tv = &g_tvec[(size_t)b * EE];
    const float* pp = &g_pair[(size_t)b * EE];
    const float* sc = &g_scores[(size_t)b * (RR + 1)];

    float part = 0.f;
    for (int e = t; e < EE; e += 256) part += tv[e] * pp[e];
    float c1000 = (bsum(part, red, t) + g_c0[0]) * NSCALE;
    __syncthreads();

    float m = -3.4e38f;
    for (int k = t; k <= RR; k += 256)
        m = fmaxf(m, (k < RR) ? sc[k] : c1000);
    m = bmax(m, red, t);
    __syncthreads();

    float se = 0.f, sv = 0.f;
    for (int k = t; k <= RR; k += 256) {
        float v = ((k < RR) ? sc[k] : c1000) - m;
        float ev = expf(v);
        se += ev; sv += ev * v;
    }
    float Z = bsum(se, red, t);
    __syncthreads();
    float S2 = bsum(sv, red, t);
    if (t == 0) loss_out[b * SS + lossidx] = logf(Z) - S2 / Z;

    float* pr = &g_prob[(size_t)b * (RR + 1)];
    for (int k = t; k <= RR; k += 256) {
        float raw = (k < RR) ? sc[k] : c1000;
        pr[k] = expf(raw - m) / Z;
        if (scores_out) scores_out[(size_t)b * (RR + 1) + k] = raw;
    }
    if (t == 0 && do_book) {
        int sel = g_sel[b];
        int* ord = &g_ord[b * SS];
        float* ps = &g_pscore[b * SS];
        int slot = ord[sel];
        g_dslot[b] = slot;
        g_src[b * SS + slot] = -1;
        for (int i = sel + 1; i < L - 1; i++) { ord[i] = ord[i + 1]; ps[i] = ps[i + 1]; }
    }
}

__device__ void ph_h1inc(int b, const float* __restrict__ b_hh) {
    int d = g_dslot[b];
    const float* gi = &g_gi[((size_t)b * SS + d) * G3];
    for (int e = threadIdx.x; e < EE; e += 256) {
        float r = sigmf(gi[e] + b_hh[e]);
        float z = sigmf(gi[EE + e] + b_hh[EE + e]);
        float n = tanhf(gi[2 * EE + e] + r * b_hh[2 * EE + e]);
        float h = (1.f - z) * n;
        g_h1[((size_t)b * SS + d) * EE + e] = h;
        g_newh1[(size_t)b * EE + e] = h;
    }
}

// =================== THE persistent rounds kernel ===================
__global__ __launch_bounds__(256) void k_rounds(
    const float* __restrict__ w_fc, const float* __restrict__ b_fc,
    const float* __restrict__ W_ih, const float* __restrict__ b_ih,
    const float* __restrict__ W_hh, const float* __restrict__ b_hh,
    float* __restrict__ out_loss, float* __restrict__ out_scores)
{
    __shared__ __align__(16) float shA[16 * 36];
    __shared__ __align__(16) float shB[16 * 68];
    __shared__ float sred[256];
    __shared__ int sord[SS];
    __shared__ float sps[SS];
    __shared__ int smisc[1];

    int bid = blockIdx.x;

    for (int i = 0; i < 15; i++) {
        int L = SS - i;
        int npairs = L - 1;
        if (bid < BB)
            ph_pairsel(bid, w_fc, b_fc, npairs, (i == 14) ? 14 : -1, out_loss, i == 0,
                       sord, sps, smisc);
        gsync();

        int nxt = (i < 14) ? 48 : 24;   // final round: scores + t only
        for (int j = bid; j < nxt * 4; j += NBLK) {
            int xt = j % nxt, yt = j / nxt;
            const float *Wp, *bp; float* op; int N, ld; float sc; int c0;
            if (xt < 16)      { Wp = g_KW;  bp = g_cs;   op = g_scores; N = RR; ld = RR + 1; sc = NSCALE; c0 = xt * 64; }
            else if (xt < 24) { Wp = g_AT;  bp = g_wvec; op = g_tvec;   N = EE; ld = EE;     sc = 1.f;    c0 = (xt - 16) * 64; }
            else              { Wp = W_ih;  bp = b_ih;   op = g_giP;    N = G3; ld = G3;     sc = 1.f;    c0 = (xt - 24) * 64; }
            job_gemm(g_pair, Wp, bp, op, N, ld, sc, c0, yt * 32, 0, shA, shB);
        }
        gsync();

        if (i == 14) {
            if (bid < BB) ph_softmax(bid, 15, 0, 0, out_loss, out_scores, sred);
            break;
        }
        if (bid < BB) ph_softmax(bid, i, L, 1, out_loss, NULL, sred);
        gsync();

        for (int j = bid; j < 96; j += NBLK)
            job_gimix((j % 24) * 64, (j / 24) * 32, shA, shB);
        gsync();

        if (bid < BB) ph_h1inc(bid, b_hh);
        gsync();

        for (int j = bid; j < 96; j += NBLK)
            job_gemm(g_newh1, W_hh, b_hh, g_ghh, G3, G3, 1.f, (j % 24) * 64, (j / 24) * 32, 1,
                     shA, shB);
        gsync();
    }
}

// ---------------- host ----------------
extern "C" void kernel_launch(void* const* d_in, const int* in_sizes, int n_in,
                              void* d_out, int out_size) {
    const int*   tokens = (const int*)  d_in[0];
    const float* emb    = (const float*)d_in[1];
    const float* W_ih   = (const float*)d_in[2];
    const float* W_hh   = (const float*)d_in[3];
    const float* b_ih   = (const float*)d_in[4];
    const float* b_hh   = (const float*)d_in[5];
    const float* w_fc   = (const float*)d_in[6];
    const float* b_fc   = (const float*)d_in[7];
    const float* Wq     = (const float*)d_in[8];
    const float* bq     = (const float*)d_in[9];
    const float* Wk     = (const float*)d_in[10];
    const float* bk     = (const float*)d_in[11];

    float* out_scores = (float*)d_out;                         // 128 x 1001
    float* out_loss   = (float*)d_out + (size_t)BB * (RR + 1); // 128 x 16

    float *GI, *H1, *Krel, *KW, *AT;
    cudaGetSymbolAddress((void**)&GI, GI_emb);
    cudaGetSymbolAddress((void**)&H1, H1_emb);
    cudaGetSymbolAddress((void**)&Krel, g_Krel);
    cudaGetSymbolAddress((void**)&KW, g_KW);
    cudaGetSymbolAddress((void**)&AT, g_AT);
    float* GHH;
    cudaGetSymbolAddress((void**)&GHH, GHH_emb);

    // ---- init (once per call) ----
    k_init<<<BB, 32>>>(tokens);
    gemm64<<<dim3(24, 16), 256>>>(emb, W_ih, b_ih, GI, RR, G3, G3, 1.f);
    k_h1emb<<<RR, 256>>>(b_hh);
    gemm64<<<dim3(24, 16), 256>>>(H1, W_hh, b_hh, GHH, RR, G3, G3, 1.f);
    gemm64<<<dim3(8, 16), 256>>>(emb, Wk, bk, Krel, RR, EE, EE, 1.f);
    k_gemm_kn<<<dim3(8, 16), 256>>>(Krel, Wq, KW, RR, EE, EE);
    k_cinit<<<125, 256>>>(bq);
    k_gemm_tn<<<dim3(8, 8), 256>>>(Wk, Wq, AT);
    k_wc<<<2, 256>>>(Wq, bq, Wk, bk);

    // ---- all 15 rounds + final attention in ONE persistent kernel ----
    k_rounds<<<NBLK, 256>>>(w_fc, b_fc, W_ih, b_ih, W_hh, b_hh, out_loss, out_scores);
}

// round 9
// speedup vs baseline: 1.1778x; 1.1717x over previous
#include <cuda_runtime.h>
#include <math.h>

#define BB 128
#define SS 16
#define EE 512
#define RR 1000
#define G3 1536
#define NSCALE 0.04419417382415922f
#define NBLK 296
#define GRPSZ 37

// ---- device scratch (static, no allocations) ----
__device__ float GI_emb[RR * G3];
__device__ float H1_emb[RR * EE];
__device__ float GHH_emb[RR * G3];
__device__ float g_Krel[RR * EE];
__device__ float g_KW[RR * EE];
__device__ float g_cs[RR];
__device__ float g_AT[EE * EE];
__device__ float g_wvec[EE];
__device__ float g_c0[1];

__device__ float g_gi [BB * SS * G3];
__device__ float g_h1 [BB * SS * EE];
__device__ float g_ghh[BB * SS * G3];

__device__ int   g_src [BB * SS];
__device__ int   g_ord [BB * SS];
__device__ int   g_sel [BB];
__device__ int   g_dslot[BB];
__device__ float g_pscore[BB * SS];

__device__ float g_pair [BB * EE];
__device__ float g_tvec [BB * EE];
__device__ float g_giP  [BB * G3];
__device__ float g_gmA  [BB * G3];
__device__ float g_gmB  [BB * G3];
__device__ float g_newh1[BB * EE];
__device__ float g_scores[BB * (RR + 1)];
__device__ float g_prob  [BB * (RR + 1) + 16];

__device__ unsigned g_cnt8[8] = {0,0,0,0,0,0,0,0};
__device__ unsigned g_root = 0;
__device__ unsigned g_gen = 0;

typedef unsigned long long ull;
__device__ __forceinline__ ull pack2(float lo, float hi) {
    ull r; asm("mov.b64 %0, {%1, %2};" : "=l"(r) : "f"(lo), "f"(hi)); return r;
}
__device__ __forceinline__ void unpack2(ull v, float& lo, float& hi) {
    asm("mov.b64 {%0, %1}, %2;" : "=f"(lo), "=f"(hi) : "l"(v));
}
#define FMA2(acc, a, b) asm("fma.rn.f32x2 %0, %1, %2, %0;" : "+l"(acc) : "l"(a), "l"(b))

__device__ __forceinline__ float sigmf(float x) { return 1.0f / (1.0f + expf(-x)); }

// ---- hierarchical grid barrier: 8 sub-counters (37 each) + root ----
__device__ __forceinline__ void gsync() {
    __syncthreads();
    if (threadIdx.x == 0) {
        __threadfence();
        unsigned gen = *((volatile unsigned*)&g_gen);
        unsigned grp = blockIdx.x & 7;
        if (atomicAdd(&g_cnt8[grp], 1u) == GRPSZ - 1) {
            if (atomicAdd(&g_root, 1u) == 7) {
#pragma unroll
                for (int i = 0; i < 8; i++) *((volatile unsigned*)&g_cnt8[i]) = 0;
                *((volatile unsigned*)&g_root) = 0;
                __threadfence();
                atomicExch(&g_gen, gen + 1);
            }
        }
        while (*((volatile unsigned*)&g_gen) == gen) {}
        __threadfence();
    }
    __syncthreads();
}

__device__ __forceinline__ const float* p_gi(int b, int s) {
    int src = g_src[b * SS + s];
    return (src >= 0) ? &GI_emb[(size_t)src * G3] : &g_gi[((size_t)b * SS + s) * G3];
}
__device__ __forceinline__ const float* p_ghh(int b, int s) {
    int src = g_src[b * SS + s];
    return (src >= 0) ? &GHH_emb[(size_t)src * G3] : &g_ghh[((size_t)b * SS + s) * G3];
}
__device__ __forceinline__ const float* p_h1(int b, int s) {
    int src = g_src[b * SS + s];
    return (src >= 0) ? &H1_emb[(size_t)src * EE] : &g_h1[((size_t)b * SS + s) * EE];
}

__global__ void k_init(const int* __restrict__ tokens) {
    int b = blockIdx.x, t = threadIdx.x;
    if (t < SS) {
        g_ord[b * SS + t] = t;
        g_src[b * SS + t] = tokens[b * SS + t];
    }
}

// ============ init-time 64x64 ping-pong GEMM (tables)
__global__ __launch_bounds__(256) void gemm64(
    const float* __restrict__ A, const float* __restrict__ W,
    const float* __restrict__ bias, float* __restrict__ out,
    int M, int N, int ldout, float scale)
{
    __shared__ __align__(16) float As[2][16][68];
    __shared__ __align__(16) float Bs[2][16][68];
    int col0 = blockIdx.x * 64, row0 = blockIdx.y * 64;
    int t = threadIdx.x, tx = t & 15, ty = t >> 4;
    ull acc[4][2];
#pragma unroll
    for (int i = 0; i < 4; i++) { acc[i][0] = 0ULL; acc[i][1] = 0ULL; }

    int am = t >> 2, akg = t & 3;
    int gmA = row0 + am, gnB = col0 + am;

    float4 ra = (gmA < M) ? *(const float4*)&A[(size_t)gmA * 512 + akg * 4]
                          : make_float4(0.f,0.f,0.f,0.f);
    float4 rb = (gnB < N) ? *(const float4*)&W[(size_t)gnB * 512 + akg * 4]
                          : make_float4(0.f,0.f,0.f,0.f);
    As[0][akg*4+0][am] = ra.x; As[0][akg*4+1][am] = ra.y;
    As[0][akg*4+2][am] = ra.z; As[0][akg*4+3][am] = ra.w;
    Bs[0][akg*4+0][am] = rb.x; Bs[0][akg*4+1][am] = rb.y;
    Bs[0][akg*4+2][am] = rb.z; Bs[0][akg*4+3][am] = rb.w;
    __syncthreads();

    for (int it = 0; it < 32; it++) {
        int cur = it & 1;
        if (it < 31) {
            int k0 = (it + 1) * 16;
            ra = (gmA < M) ? *(const float4*)&A[(size_t)gmA * 512 + k0 + akg * 4]
                           : make_float4(0.f,0.f,0.f,0.f);
            rb = (gnB < N) ? *(const float4*)&W[(size_t)gnB * 512 + k0 + akg * 4]
                           : make_float4(0.f,0.f,0.f,0.f);
        }
#pragma unroll
        for (int kk = 0; kk < 16; kk++) {
            ull b0 = *(const ull*)&Bs[cur][kk][tx*4];
            ull b1 = *(const ull*)&Bs[cur][kk][tx*4+2];
            float4 a = *(const float4*)&As[cur][kk][ty*4];
            ull a0=pack2(a.x,a.x), a1=pack2(a.y,a.y);
            ull a2=pack2(a.z,a.z), a3=pack2(a.w,a.w);
            FMA2(acc[0][0],a0,b0); FMA2(acc[0][1],a0,b1);
            FMA2(acc[1][0],a1,b0); FMA2(acc[1][1],a1,b1);
            FMA2(acc[2][0],a2,b0); FMA2(acc[2][1],a2,b1);
            FMA2(acc[3][0],a3,b0); FMA2(acc[3][1],a3,b1);
        }
        if (it < 31) {
            int nxt = 1 - cur;
            As[nxt][akg*4+0][am] = ra.x; As[nxt][akg*4+1][am] = ra.y;
            As[nxt][akg*4+2][am] = ra.z; As[nxt][akg*4+3][am] = ra.w;
            Bs[nxt][akg*4+0][am] = rb.x; Bs[nxt][akg*4+1][am] = rb.y;
            Bs[nxt][akg*4+2][am] = rb.z; Bs[nxt][akg*4+3][am] = rb.w;
        }
        __syncthreads();
    }
#pragma unroll
    for (int i = 0; i < 4; i++) {
        int gm = row0 + ty * 4 + i;
        if (gm >= M) continue;
        float* orow = out + (size_t)gm * (size_t)ldout;
#pragma unroll
        for (int j = 0; j < 2; j++) {
            float lo, hi;
            unpack2(acc[i][j], lo, hi);
            int c = col0 + tx * 4 + j * 2;
            if (c < N)     orow[c]     = lo * scale + (bias ? bias[c]     : 0.f);
            if (c + 1 < N) orow[c + 1] = hi * scale + (bias ? bias[c + 1] : 0.f);
        }
    }
}

// ============ KW = Krel @ Wq (B K-row-major)
__global__ __launch_bounds__(256) void k_gemm_kn(
    const float* __restrict__ A, const float* __restrict__ B,
    float* __restrict__ out, int M, int N, int ldb)
{
    __shared__ __align__(16) float As[16][68];
    __shared__ __align__(16) float Bs[16][68];
    int col0 = blockIdx.x * 64, row0 = blockIdx.y * 64;
    int t = threadIdx.x, tx = t & 15, ty = t >> 4;
    ull acc[4][2];
#pragma unroll
    for (int i = 0; i < 4; i++) { acc[i][0] = 0ULL; acc[i][1] = 0ULL; }

    int am = t >> 2, akg = t & 3;
    int gmA = row0 + am;
    int kkB = t >> 4, ngB = t & 15;

    for (int k0 = 0; k0 < 512; k0 += 16) {
        float4 ra = (gmA < M) ? *(const float4*)&A[(size_t)gmA*512 + k0 + akg*4]
                              : make_float4(0.f,0.f,0.f,0.f);
        float4 rb = *(const float4*)&B[(size_t)(k0 + kkB) * ldb + col0 + ngB * 4];
        As[akg*4+0][am] = ra.x; As[akg*4+1][am] = ra.y;
        As[akg*4+2][am] = ra.z; As[akg*4+3][am] = ra.w;
        Bs[kkB][ngB*4+0] = rb.x; Bs[kkB][ngB*4+1] = rb.y;
        Bs[kkB][ngB*4+2] = rb.z; Bs[kkB][ngB*4+3] = rb.w;
        __syncthreads();
#pragma unroll
        for (int kk = 0; kk < 16; kk++) {
            ull b0 = *(const ull*)&Bs[kk][tx*4];
            ull b1 = *(const ull*)&Bs[kk][tx*4+2];
            float4 a = *(const float4*)&As[kk][ty*4];
            ull a0=pack2(a.x,a.x), a1=pack2(a.y,a.y);
            ull a2=pack2(a.z,a.z), a3=pack2(a.w,a.w);
            FMA2(acc[0][0],a0,b0); FMA2(acc[0][1],a0,b1);
            FMA2(acc[1][0],a1,b0); FMA2(acc[1][1],a1,b1);
            FMA2(acc[2][0],a2,b0); FMA2(acc[2][1],a2,b1);
            FMA2(acc[3][0],a3,b0); FMA2(acc[3][1],a3,b1);
        }
        __syncthreads();
    }
#pragma unroll
    for (int i = 0; i < 4; i++) {
        int gm = row0 + ty * 4 + i;
        if (gm >= M) continue;
#pragma unroll
        for (int j = 0; j < 2; j++) {
            float lo, hi;
            unpack2(acc[i][j], lo, hi);
            int c = col0 + tx * 4 + j * 2;
            if (c < N)     out[(size_t)gm * N + c]     = lo;
            if (c + 1 < N) out[(size_t)gm * N + c + 1] = hi;
        }
    }
}

// ============ AT[m][n] = sum_k Wk[k][m] * Wq[k][n]
__global__ __launch_bounds__(256) void k_gemm_tn(
    const float* __restrict__ P, const float* __restrict__ Q, float* __restrict__ out)
{
    __shared__ __align__(16) float As[16][68];
    __shared__ __align__(16) float Bs[16][68];
    int col0 = blockIdx.x * 64, row0 = blockIdx.y * 64;
    int t = threadIdx.x, tx = t & 15, ty = t >> 4;
    ull acc[4][2];
#pragma unroll
    for (int i = 0; i < 4; i++) { acc[i][0] = 0ULL; acc[i][1] = 0ULL; }
    int kk0 = t >> 4, g = t & 15;

    for (int k0 = 0; k0 < 512; k0 += 16) {
        float4 ra = *(const float4*)&P[(size_t)(k0 + kk0) * 512 + row0 + g * 4];
        float4 rb = *(const float4*)&Q[(size_t)(k0 + kk0) * 512 + col0 + g * 4];
        As[kk0][g*4+0] = ra.x; As[kk0][g*4+1] = ra.y;
        As[kk0][g*4+2] = ra.z; As[kk0][g*4+3] = ra.w;
        Bs[kk0][g*4+0] = rb.x; Bs[kk0][g*4+1] = rb.y;
        Bs[kk0][g*4+2] = rb.z; Bs[kk0][g*4+3] = rb.w;
        __syncthreads();
#pragma unroll
        for (int kk = 0; kk < 16; kk++) {
            ull b0 = *(const ull*)&Bs[kk][tx*4];
            ull b1 = *(const ull*)&Bs[kk][tx*4+2];
            float4 a = *(const float4*)&As[kk][ty*4];
            ull a0=pack2(a.x,a.x), a1=pack2(a.y,a.y);
            ull a2=pack2(a.z,a.z), a3=pack2(a.w,a.w);
            FMA2(acc[0][0],a0,b0); FMA2(acc[0][1],a0,b1);
            FMA2(acc[1][0],a1,b0); FMA2(acc[1][1],a1,b1);
            FMA2(acc[2][0],a2,b0); FMA2(acc[2][1],a2,b1);
            FMA2(acc[3][0],a3,b0); FMA2(acc[3][1],a3,b1);
        }
        __syncthreads();
    }
#pragma unroll
    for (int i = 0; i < 4; i++) {
        int gm = row0 + ty * 4 + i;
#pragma unroll
        for (int j = 0; j < 2; j++) {
            float lo, hi;
            unpack2(acc[i][j], lo, hi);
            int c = col0 + tx * 4 + j * 2;
            out[(size_t)gm * 512 + c]     = lo;
            out[(size_t)gm * 512 + c + 1] = hi;
        }
    }
}

__global__ void k_wc(const float* __restrict__ Wq, const float* __restrict__ bq,
                     const float* __restrict__ Wk, const float* __restrict__ bk) {
    __shared__ float red[256];
    int t = threadIdx.x;
    int i = blockIdx.x * 256 + t;
    float acc = 0.f;
    for (int n = 0; n < EE; n++)
        acc += Wq[(size_t)n * EE + i] * bk[n] + Wk[(size_t)n * EE + i] * bq[n];
    g_wvec[i] = acc;
    if (blockIdx.x == 0) {
        float p = 0.f;
        for (int n = t; n < EE; n += 256) p += bq[n] * bk[n];
        red[t] = p; __syncthreads();
        for (int s = 128; s > 0; s >>= 1) { if (t < s) red[t] += red[t + s]; __syncthreads(); }
        if (t == 0) g_c0[0] = red[0];
    }
}

__global__ void k_h1emb(const float* __restrict__ b_hh) {
    int tk = blockIdx.x;
    const float* gi = &GI_emb[(size_t)tk * G3];
    for (int e = threadIdx.x; e < EE; e += blockDim.x) {
        float r = sigmf(gi[e] + b_hh[e]);
        float z = sigmf(gi[EE + e] + b_hh[EE + e]);
        float n = tanhf(gi[2 * EE + e] + r * b_hh[2 * EE + e]);
        H1_emb[(size_t)tk * EE + e] = (1.f - z) * n;
    }
}

__global__ void k_cinit(const float* __restrict__ bq) {
    int r = blockIdx.x * 8 + (threadIdx.x >> 5);
    int lane = threadIdx.x & 31;
    if (r >= RR) return;
    float s = 0.f;
    for (int e = lane; e < EE; e += 32) s += bq[e] * g_Krel[(size_t)r * EE + e];
#pragma unroll
    for (int off = 16; off > 0; off >>= 1) s += __shfl_down_sync(0xffffffffu, s, off);
    if (lane == 0) g_cs[r] = NSCALE * s;
}

// =================== persistent-round device functions ===================

__device__ __forceinline__ float pair_elem(const float* gi, const float* gh,
                                           const float* h1, int e) {
    float r = sigmf(gi[e] + gh[e]);
    float z = sigmf(gi[EE + e] + gh[EE + e]);
    float n = tanhf(gi[2 * EE + e] + r * gh[2 * EE + e]);
    return (1.f - z) * n + z * h1[e];
}

// TM=32/TN=64 GEMM job, K=512.
__device__ __noinline__ void job_gemm(const float* __restrict__ A, const float* __restrict__ Wp,
                                      const float* __restrict__ bp, float* __restrict__ op,
                                      int N, int ld, float scale, int col0, int row0,
                                      int scatter, float* shA, float* shB)
{
    int t = threadIdx.x, tx = t & 15, ty = t >> 4;
    ull a00 = 0ULL, a01 = 0ULL, a10 = 0ULL, a11 = 0ULL;
    int am = t >> 2, akg = t & 3;
    bool hasA = (t < 128);
    int gmA = row0 + am;
    int gnB = col0 + (t >> 2);
    int bkg = t & 3;

    float4 ra = hasA ? *(const float4*)&A[(size_t)gmA * 512 + akg * 4]
                     : make_float4(0.f,0.f,0.f,0.f);
    float4 rb = (gnB < N) ? *(const float4*)&Wp[(size_t)gnB * 512 + bkg * 4]
                          : make_float4(0.f,0.f,0.f,0.f);

    for (int it = 0; it < 32; it++) {
        if (hasA) {
            shA[(akg*4+0)*36+am] = ra.x; shA[(akg*4+1)*36+am] = ra.y;
            shA[(akg*4+2)*36+am] = ra.z; shA[(akg*4+3)*36+am] = ra.w;
        }
        int bn = t >> 2;
        shB[(bkg*4+0)*68+bn] = rb.x; shB[(bkg*4+1)*68+bn] = rb.y;
        shB[(bkg*4+2)*68+bn] = rb.z; shB[(bkg*4+3)*68+bn] = rb.w;
        __syncthreads();
        if (it < 31) {
            int k0 = (it + 1) * 16;
            if (hasA) ra = *(const float4*)&A[(size_t)gmA * 512 + k0 + akg * 4];
            rb = (gnB < N) ? *(const float4*)&Wp[(size_t)gnB * 512 + k0 + bkg * 4]
                           : make_float4(0.f,0.f,0.f,0.f);
        }
#pragma unroll
        for (int kk = 0; kk < 16; kk++) {
            ull b0 = *(const ull*)&shB[kk*68 + tx*4];
            ull b1 = *(const ull*)&shB[kk*68 + tx*4 + 2];
            float2 a = *(const float2*)&shA[kk*36 + ty*2];
            ull q0 = pack2(a.x, a.x), q1 = pack2(a.y, a.y);
            FMA2(a00, q0, b0); FMA2(a01, q0, b1);
            FMA2(a10, q1, b0); FMA2(a11, q1, b1);
        }
        __syncthreads();
    }
#pragma unroll
    for (int i = 0; i < 2; i++) {
        int gm = row0 + ty * 2 + i;
        float* orow = scatter ? op + ((size_t)gm * SS + g_dslot[gm]) * (size_t)ld
                              : op + (size_t)gm * (size_t)ld;
        ull v0 = i ? a10 : a00, v1 = i ? a11 : a01;
#pragma unroll
        for (int j = 0; j < 2; j++) {
            float lo, hi;
            unpack2(j ? v1 : v0, lo, hi);
            int c = col0 + tx * 4 + j * 2;
            if (c < N)     orow[c]     = lo * scale + bp[c];
            if (c + 1 < N) orow[c + 1] = hi * scale + bp[c + 1];
        }
    }
}

// gimix split-K partial: out = prob[:, kbase:kbase+len] @ GI_emb[kbase:kbase+len, :]
__device__ __noinline__ void job_gimix_part(int slice, int col0, int row0,
                                            float* shA, float* shB)
{
    int t = threadIdx.x, tx = t & 15, ty = t >> 4;
    ull a00 = 0ULL, a01 = 0ULL, a10 = 0ULL, a11 = 0ULL;
    int am = t >> 2, akg = t & 3;
    bool hasA = (t < 128);
    int gmA = row0 + am;
    int kkB = t >> 4, ngB = t & 15;
    const float* prow = &g_prob[(size_t)(hasA ? gmA : 0) * (RR + 1)];
    int kbase = slice * 512;
    int NIT = slice ? 31 : 32;   // [0,512) and [512,1000)

    float pa[4];
#pragma unroll
    for (int u = 0; u < 4; u++) {
        int k = kbase + akg * 4 + u;
        pa[u] = (hasA && k < RR) ? prow[k] : 0.f;
    }
    int kb0 = kbase + kkB;
    float4 rb = (kb0 < RR) ? *(const float4*)&GI_emb[(size_t)kb0 * G3 + col0 + ngB * 4]
                           : make_float4(0.f,0.f,0.f,0.f);

    for (int it = 0; it < NIT; it++) {
        if (hasA) {
            shA[(akg*4+0)*36+am] = pa[0]; shA[(akg*4+1)*36+am] = pa[1];
            shA[(akg*4+2)*36+am] = pa[2]; shA[(akg*4+3)*36+am] = pa[3];
        }
        shB[kkB*68 + ngB*4 + 0] = rb.x; shB[kkB*68 + ngB*4 + 1] = rb.y;
        shB[kkB*68 + ngB*4 + 2] = rb.z; shB[kkB*68 + ngB*4 + 3] = rb.w;
        __syncthreads();
        if (it < NIT - 1) {
            int k0 = kbase + (it + 1) * 16;
#pragma unroll
            for (int u = 0; u < 4; u++) {
                int k = k0 + akg * 4 + u;
                pa[u] = (hasA && k < RR) ? prow[k] : 0.f;
            }
            int kb = k0 + kkB;
            rb = (kb < RR) ? *(const float4*)&GI_emb[(size_t)kb * G3 + col0 + ngB * 4]
                           : make_float4(0.f,0.f,0.f,0.f);
        }
#pragma unroll
        for (int kk = 0; kk < 16; kk++) {
            ull b0 = *(const ull*)&shB[kk*68 + tx*4];
            ull b1 = *(const ull*)&shB[kk*68 + tx*4 + 2];
            float2 a = *(const float2*)&shA[kk*36 + ty*2];
            ull q0 = pack2(a.x, a.x), q1 = pack2(a.y, a.y);
            FMA2(a00, q0, b0); FMA2(a01, q0, b1);
            FMA2(a10, q1, b0); FMA2(a11, q1, b1);
        }
        __syncthreads();
    }
    float* out = slice ? g_gmB : g_gmA;
#pragma unroll
    for (int i = 0; i < 2; i++) {
        int gm = row0 + ty * 2 + i;
        float* orow = out + (size_t)gm * G3;
        ull v0 = i ? a10 : a00, v1 = i ? a11 : a01;
#pragma unroll
        for (int j = 0; j < 2; j++) {
            float lo, hi;
            unpack2(j ? v1 : v0, lo, hi);
            int c = col0 + tx * 4 + j * 2;
            orow[c]     = lo;
            orow[c + 1] = hi;
        }
    }
}

__device__ __noinline__ void ph_pairsel(int b, const float* __restrict__ wfc,
                                        const float* __restrict__ bfc,
                                        int npairs, int zloss, float* __restrict__ loss_out,
                                        int first, int* sord, float* sps, int* smisc)
{
    int t = threadIdx.x;
    int w = t >> 5, lane = t & 31;
    if (t < SS) {
        sord[t] = g_ord[b * SS + t];
        sps[t]  = g_pscore[b * SS + t];
    }
    int prev_sel = g_sel[b];
    __syncthreads();

    int j0 = -1, j1 = -1;
    if (first) {
        j0 = w;  j1 = w + 8;
        if (j0 >= npairs) j0 = -1;
        if (j1 >= npairs) j1 = -1;
    } else {
        int cnt = 0, jj[2];
        if (prev_sel - 1 >= 0 && prev_sel - 1 < npairs) jj[cnt++] = prev_sel - 1;
        if (prev_sel >= 0 && prev_sel < npairs)         jj[cnt++] = prev_sel;
        if (w < cnt) j0 = jj[w];
    }
#pragma unroll
    for (int rep = 0; rep < 2; rep++) {
        int j = (rep == 0) ? j0 : j1;
        if (j >= 0) {
            const float* gi = p_gi(b, sord[j + 1]);
            const float* gh = p_ghh(b, sord[j]);
            const float* h1 = p_h1(b, sord[j]);
            float s = 0.f;
            for (int e = lane; e < EE; e += 32)
                s += pair_elem(gi, gh, h1, e) * wfc[e];
#pragma unroll
            for (int off = 16; off > 0; off >>= 1)
                s += __shfl_down_sync(0xffffffffu, s, off);
            if (lane == 0) {
                float sc = sigmf(s + bfc[0]);
                sps[j] = sc;
                g_pscore[b * SS + j] = sc;
            }
        }
    }
    __syncthreads();

    if (t == 0) {
        int bj = 0; float bs = sps[0];
        for (int j = 1; j < npairs; j++)
            if (sps[j] > bs) { bs = sps[j]; bj = j; }
        smisc[0] = bj;
        g_sel[b] = bj;
        if (zloss >= 0) loss_out[b * SS + zloss] = 0.f;
    }
    __syncthreads();
    int j = smisc[0];
    const float* gi = p_gi(b, sord[j + 1]);
    const float* gh = p_ghh(b, sord[j]);
    const float* h1 = p_h1(b, sord[j]);
    for (int e = t; e < EE; e += 256)
        g_pair[(size_t)b * EE + e] = pair_elem(gi, gh, h1, e);
}

__device__ __forceinline__ float bsum(float v, float* red, int t) {
    red[t] = v; __syncthreads();
    for (int s = 128; s > 0; s >>= 1) { if (t < s) red[t] += red[t + s]; __syncthreads(); }
    return red[0];
}
__device__ __forceinline__ float bmax(float v, float* red, int t) {
    red[t] = v; __syncthreads();
    for (int s = 128; s > 0; s >>= 1) { if (t < s) red[t] = fmaxf(red[t], red[t + s]); __syncthreads(); }
    return red[0];
}

__device__ __noinline__ void ph_softmax(int b, int lossidx, int L, int do_book,
                                        float* __restrict__ loss_out,
                                        float* __restrict__ scores_out, float* red)
{
    int t = threadIdx.x;
    const float* tv = &g_tvec[(size_t)b * EE];
    const float* pp = &g_pair[(size_t)b * EE];
    const float* sc = &g_scores[(size_t)b * (RR + 1)];

    float part = 0.f;
    for (int e = t; e < EE; e += 256) part += tv[e] * pp[e];
    float c1000 = (bsum(part, red, t) + g_c0[0]) * NSCALE;
    __syncthreads();

    float m = -3.4e38f;
    for (int k = t; k <= RR; k += 256)
        m = fmaxf(m, (k < RR) ? sc[k] : c1000);
    m = bmax(m, red, t);
    __syncthreads();

    float se = 0.f, sv = 0.f;
    for (int k = t; k <= RR; k += 256) {
        float v = ((k < RR) ? sc[k] : c1000) - m;
        float ev = expf(v);
        se += ev; sv += ev * v;
    }
    float Z = bsum(se, red, t);
    __syncthreads();
    float S2 = bsum(sv, red, t);
    if (t == 0) loss_out[b * SS + lossidx] = logf(Z) - S2 / Z;

    float* pr = &g_prob[(size_t)b * (RR + 1)];
    for (int k = t; k <= RR; k += 256) {
        float raw = (k < RR) ? sc[k] : c1000;
        pr[k] = expf(raw - m) / Z;
        if (scores_out) scores_out[(size_t)b * (RR + 1) + k] = raw;
    }
    if (t == 0 && do_book) {
        int sel = g_sel[b];
        int* ord = &g_ord[b * SS];
        float* ps = &g_pscore[b * SS];
        int slot = ord[sel];
        g_dslot[b] = slot;
        g_src[b * SS + slot] = -1;
        for (int i = sel + 1; i < L - 1; i++) { ord[i] = ord[i + 1]; ps[i] = ps[i + 1]; }
    }
}

// finalize gi (sum partials + pp*giP), scatter to g_gi, and compute h1 from smem copy
__device__ __noinline__ void ph_fin(int b, const float* __restrict__ b_hh, float* sgi)
{
    int t = threadIdx.x;
    int slot = g_dslot[b];
    float pp = g_prob[(size_t)b * (RR + 1) + RR];
    float* orow = &g_gi[((size_t)b * SS + slot) * G3];
    const float* pA = &g_gmA[(size_t)b * G3];
    const float* pB = &g_gmB[(size_t)b * G3];
    const float* gp = &g_giP[(size_t)b * G3];
    for (int e = t; e < G3; e += 256) {
        float v = pA[e] + pB[e] + pp * gp[e];
        sgi[e] = v;
        orow[e] = v;
    }
    __syncthreads();
    for (int e = t; e < EE; e += 256) {
        float r = sigmf(sgi[e] + b_hh[e]);
        float z = sigmf(sgi[EE + e] + b_hh[EE + e]);
        float n = tanhf(sgi[2 * EE + e] + r * b_hh[2 * EE + e]);
        float h = (1.f - z) * n;
        g_h1[((size_t)b * SS + slot) * EE + e] = h;
        g_newh1[(size_t)b * EE + e] = h;
    }
}

// =================== THE persistent rounds kernel ===================
__global__ __launch_bounds__(256, 2) void k_rounds(
    const float* __restrict__ w_fc, const float* __restrict__ b_fc,
    const float* __restrict__ W_ih, const float* __restrict__ b_ih,
    const float* __restrict__ W_hh, const float* __restrict__ b_hh,
    float* __restrict__ out_loss, float* __restrict__ out_scores)
{
    __shared__ __align__(16) float shA[16 * 36];
    __shared__ __align__(16) float shB[16 * 68];
    __shared__ __align__(16) float sgi[G3];
    __shared__ float sred[256];
    __shared__ int sord[SS];
    __shared__ float sps[SS];
    __shared__ int smisc[1];

    int bid = blockIdx.x;

    for (int i = 0; i < 15; i++) {
        int L = SS - i;
        int npairs = L - 1;

        // P1: pairsel
        if (bid < BB)
            ph_pairsel(bid, w_fc, b_fc, npairs, (i == 14) ? 14 : -1, out_loss, i == 0,
                       sord, sps, smisc);
        gsync();

        // P2: scores (16 xt) + tvec (8 xt), 96 jobs
        if (bid < 96) {
            int xt = bid % 24, yt = bid / 24;
            if (xt < 16)
                job_gemm(g_pair, g_KW, g_cs, g_scores, RR, RR + 1, NSCALE,
                         xt * 64, yt * 32, 0, shA, shB);
            else
                job_gemm(g_pair, g_AT, g_wvec, g_tvec, EE, EE, 1.f,
                         (xt - 16) * 64, yt * 32, 0, shA, shB);
        }
        gsync();

        if (i == 14) {
            if (bid < BB) ph_softmax(bid, 15, 0, 0, out_loss, out_scores, sred);
            break;
        }

        // P3: softmax (blocks 0..127)  ||  giP = pair@W_ih^T + b_ih (blocks 128..223)
        if (bid < BB) {
            ph_softmax(bid, i, L, 1, out_loss, NULL, sred);
        } else if (bid < BB + 96) {
            int j = bid - BB;
            job_gemm(g_pair, W_ih, b_ih, g_giP, G3, G3, 1.f,
                     (j % 24) * 64, (j / 24) * 32, 0, shA, shB);
        }
        gsync();

        // P4: gimix split-K partials, 192 jobs
        if (bid < 192) {
            int slice = bid / 96, j = bid % 96;
            job_gimix_part(slice, (j % 24) * 64, (j / 24) * 32, shA, shB);
        }
        gsync();

        // P5: finalize gi + h1 (fused), per-batch
        if (bid < BB) ph_fin(bid, b_hh, sgi);
        gsync();

        // P6: ghh = newh1 @ W_hh^T + b_hh (scattered), 96 jobs
        if (bid < 96) {
            int xt = bid % 24, yt = bid / 24;
            job_gemm(g_newh1, W_hh, b_hh, g_ghh, G3, G3, 1.f,
                     xt * 64, yt * 32, 1, shA, shB);
        }
        gsync();
    }
}

// ---------------- host ----------------
extern "C" void kernel_launch(void* const* d_in, const int* in_sizes, int n_in,
                              void* d_out, int out_size) {
    const int*   tokens = (const int*)  d_in[0];
    const float* emb    = (const float*)d_in[1];
    const float* W_ih   = (const float*)d_in[2];
    const float* W_hh   = (const float*)d_in[3];
    const float* b_ih   = (const float*)d_in[4];
    const float* b_hh   = (const float*)d_in[5];
    const float* w_fc   = (const float*)d_in[6];
    const float* b_fc   = (const float*)d_in[7];
    const float* Wq     = (const float*)d_in[8];
    const float* bq     = (const float*)d_in[9];
    const float* Wk     = (const float*)d_in[10];
    const float* bk     = (const float*)d_in[11];

    float* out_scores = (float*)d_out;                         // 128 x 1001
    float* out_loss   = (float*)d_out + (size_t)BB * (RR + 1); // 128 x 16

    float *GI, *H1, *GHH, *Krel, *KW, *AT;
    cudaGetSymbolAddress((void**)&GI, GI_emb);
    cudaGetSymbolAddress((void**)&H1, H1_emb);
    cudaGetSymbolAddress((void**)&GHH, GHH_emb);
    cudaGetSymbolAddress((void**)&Krel, g_Krel);
    cudaGetSymbolAddress((void**)&KW, g_KW);
    cudaGetSymbolAddress((void**)&AT, g_AT);

    // ---- init (once per call) ----
    k_init<<<BB, 32>>>(tokens);
    gemm64<<<dim3(24, 16), 256>>>(emb, W_ih, b_ih, GI, RR, G3, G3, 1.f);
    k_h1emb<<<RR, 256>>>(b_hh);
    gemm64<<<dim3(24, 16), 256>>>(H1, W_hh, b_hh, GHH, RR, G3, G3, 1.f);
    gemm64<<<dim3(8, 16), 256>>>(emb, Wk, bk, Krel, RR, EE, EE, 1.f);
    k_gemm_kn<<<dim3(8, 16), 256>>>(Krel, Wq, KW, RR, EE, EE);
    k_cinit<<<125, 256>>>(bq);
    k_gemm_tn<<<dim3(8, 8), 256>>>(Wk, Wq, AT);
    k_wc<<<2, 256>>>(Wq, bq, Wk, bk);

    // ---- all 15 rounds + final attention in ONE persistent kernel ----
    k_rounds<<<NBLK, 256>>>(w_fc, b_fc, W_ih, b_ih, W_hh, b_hh, out_loss, out_scores);
}

// round 10
// speedup vs baseline: 1.3535x; 1.1491x over previous
#include <cuda_runtime.h>
#include <math.h>

#define BB 128
#define SS 16
#define EE 512
#define RR 1000
#define G3 1536
#define NSCALE 0.04419417382415922f

// ---- device scratch (static, no allocations) ----
__device__ float GI_emb[RR * G3];
__device__ float H1_emb[RR * EE];
__device__ float GHH_emb[RR * G3];
__device__ float g_Krel[RR * EE];
__device__ float g_KW[RR * EE];
__device__ float g_cs[RR];
__device__ float g_AT[EE * EE];
__device__ float g_wvec[EE];
__device__ float g_c0[1];

__device__ float g_gi [BB * SS * G3];
__device__ float g_h1 [BB * SS * EE];
__device__ float g_ghh[BB * SS * G3];

__device__ int   g_src [BB * SS];
__device__ int   g_ord [BB * SS];
__device__ int   g_sel [BB];
__device__ int   g_dslot[BB];
__device__ float g_pscore[BB * SS];

__device__ float g_pair [BB * EE];
__device__ float g_newh1[BB * EE];
__device__ float g_prob [BB * (RR + 1) + 16];

// split-K partial buffers
__device__ float g_sc0[BB * RR];
__device__ float g_sc1[BB * RR];
__device__ float g_tv0[BB * EE];
__device__ float g_tv1[BB * EE];
__device__ float g_gp0[BB * G3];
__device__ float g_gp1[BB * G3];
__device__ float g_gm4[4][BB * G3];
__device__ float g_gh0[BB * G3];
__device__ float g_gh1[BB * G3];

typedef unsigned long long ull;
__device__ __forceinline__ ull pack2(float lo, float hi) {
    ull r; asm("mov.b64 %0, {%1, %2};" : "=l"(r) : "f"(lo), "f"(hi)); return r;
}
__device__ __forceinline__ void unpack2(ull v, float& lo, float& hi) {
    asm("mov.b64 {%0, %1}, %2;" : "=f"(lo), "=f"(hi) : "l"(v));
}
#define FMA2(acc, a, b) asm("fma.rn.f32x2 %0, %1, %2, %0;" : "+l"(acc) : "l"(a), "l"(b))

__device__ __forceinline__ float sigmf(float x) { return 1.0f / (1.0f + expf(-x)); }

__device__ __forceinline__ const float* p_gi(int b, int s) {
    int src = g_src[b * SS + s];
    return (src >= 0) ? &GI_emb[(size_t)src * G3] : &g_gi[((size_t)b * SS + s) * G3];
}
__device__ __forceinline__ const float* p_ghh(int b, int s) {
    int src = g_src[b * SS + s];
    return (src >= 0) ? &GHH_emb[(size_t)src * G3] : &g_ghh[((size_t)b * SS + s) * G3];
}
__device__ __forceinline__ const float* p_h1(int b, int s) {
    int src = g_src[b * SS + s];
    return (src >= 0) ? &H1_emb[(size_t)src * EE] : &g_h1[((size_t)b * SS + s) * EE];
}

__global__ void k_init(const int* __restrict__ tokens) {
    int b = blockIdx.x, t = threadIdx.x;
    if (t < SS) {
        g_ord[b * SS + t] = t;
        g_src[b * SS + t] = tokens[b * SS + t];
    }
}

// ======================================================================
// Per-round GEMM: 64x64 tile, 4x4 f32x2 reg tile, dup-A smem, conflict-free.
// Phases select operands; output is a raw split-K partial (no bias/scale).
// ======================================================================
#define PH_BGA   0   // A=g_pair  : xt<16 scores(KW), xt<24 tvec(AT), xt<48 giP(W_ih)
#define PH_GIMIX 1   // A=g_prob (ld 1001, K=1000), B=GI_emb (K-major)
#define PH_GHH   2   // A=g_newh1, B=W_hh

__global__ __launch_bounds__(256) void k_mm(int phase,
    const float* __restrict__ W_ih, const float* __restrict__ W_hh)
{
    __shared__ __align__(16) float shA[16][136];
    __shared__ __align__(16) float shB[16][68];
    int t = threadIdx.x, tx = t & 15, ty = t >> 4;
    int xt = blockIdx.x, yt = blockIdx.y, ks = blockIdx.z;

    const float* A = g_pair; int lda = 512, Ktot = 512, mode = 0;
    const float* W; float* out; int N, wld, kn = 0;
    if (phase == PH_BGA) {
        wld = 512;
        if (xt < 16)      { W = g_KW;  out = ks ? g_sc1 : g_sc0; N = RR; }
        else if (xt < 24) { W = g_AT;  out = ks ? g_tv1 : g_tv0; N = EE; xt -= 16; }
        else              { W = W_ih;  out = ks ? g_gp1 : g_gp0; N = G3; xt -= 24; }
    } else if (phase == PH_GIMIX) {
        A = g_prob; lda = RR + 1; Ktot = RR; mode = 1; kn = 1;
        W = GI_emb; wld = G3; out = g_gm4[ks]; N = G3;
    } else {
        A = g_newh1; W = W_hh; wld = 512; out = ks ? g_gh1 : g_gh0; N = G3;
    }
    int kb = ks * 256;
    int col0 = xt * 64, row0 = yt * 64;

    ull acc[4][2];
#pragma unroll
    for (int i = 0; i < 4; i++) { acc[i][0] = 0ULL; acc[i][1] = 0ULL; }

    int am = t >> 2, akg = t & 3;
    int gmA = row0 + am;
    int bn = t >> 2, bkg = t & 3;       // kn==0 (W is N-row-major)
    int kkB = t >> 4, ngB = t & 15;     // kn==1 (W is K-row-major)

    float pa[4];
    float4 rb;
    if (mode == 0) {
        float4 v = *(const float4*)&A[(size_t)gmA * lda + kb + akg * 4];
        pa[0] = v.x; pa[1] = v.y; pa[2] = v.z; pa[3] = v.w;
    } else {
#pragma unroll
        for (int u = 0; u < 4; u++) {
            int k = kb + akg * 4 + u;
            pa[u] = (k < Ktot) ? A[(size_t)gmA * lda + k] : 0.f;
        }
    }
    if (kn == 0) {
        int gn = col0 + bn;
        rb = (gn < N) ? *(const float4*)&W[(size_t)gn * wld + kb + bkg * 4]
                      : make_float4(0.f, 0.f, 0.f, 0.f);
    } else {
        int k = kb + kkB;
        rb = (k < Ktot) ? *(const float4*)&W[(size_t)k * wld + col0 + ngB * 4]
                        : make_float4(0.f, 0.f, 0.f, 0.f);
    }

    for (int it = 0; it < 16; it++) {
        // A stored duplicated: shA[kk][m*2..m*2+1] = (a, a)
#pragma unroll
        for (int u = 0; u < 4; u++)
            *(ull*)&shA[akg * 4 + u][am * 2] = pack2(pa[u], pa[u]);
        if (kn == 0) {
            shB[bkg*4+0][bn] = rb.x; shB[bkg*4+1][bn] = rb.y;
            shB[bkg*4+2][bn] = rb.z; shB[bkg*4+3][bn] = rb.w;
        } else {
            *(float4*)&shB[kkB][ngB * 4] = rb;
        }
        __syncthreads();
        if (it < 15) {
            int k0 = kb + (it + 1) * 16;
            if (mode == 0) {
                float4 v = *(const float4*)&A[(size_t)gmA * lda + k0 + akg * 4];
                pa[0] = v.x; pa[1] = v.y; pa[2] = v.z; pa[3] = v.w;
            } else {
#pragma unroll
                for (int u = 0; u < 4; u++) {
                    int k = k0 + akg * 4 + u;
                    pa[u] = (k < Ktot) ? A[(size_t)gmA * lda + k] : 0.f;
                }
            }
            if (kn == 0) {
                int gn = col0 + bn;
                rb = (gn < N) ? *(const float4*)&W[(size_t)gn * wld + k0 + bkg * 4]
                              : make_float4(0.f, 0.f, 0.f, 0.f);
            } else {
                int k = k0 + kkB;
                rb = (k < Ktot) ? *(const float4*)&W[(size_t)k * wld + col0 + ngB * 4]
                                : make_float4(0.f, 0.f, 0.f, 0.f);
            }
        }
#pragma unroll
        for (int kk = 0; kk < 16; kk++) {
            ulonglong2 bv  = *(const ulonglong2*)&shB[kk][tx * 4];
            ulonglong2 a01 = *(const ulonglong2*)&shA[kk][ty * 8];
            ulonglong2 a23 = *(const ulonglong2*)&shA[kk][ty * 8 + 4];
            FMA2(acc[0][0], a01.x, bv.x); FMA2(acc[0][1], a01.x, bv.y);
            FMA2(acc[1][0], a01.y, bv.x); FMA2(acc[1][1], a01.y, bv.y);
            FMA2(acc[2][0], a23.x, bv.x); FMA2(acc[2][1], a23.x, bv.y);
            FMA2(acc[3][0], a23.y, bv.x); FMA2(acc[3][1], a23.y, bv.y);
        }
        __syncthreads();
    }
#pragma unroll
    for (int i = 0; i < 4; i++) {
        int gm = row0 + ty * 4 + i;
        float* orow = out + (size_t)gm * N;
#pragma unroll
        for (int j = 0; j < 2; j++) {
            float lo, hi;
            unpack2(acc[i][j], lo, hi);
            int c = col0 + tx * 4 + j * 2;
            if (c < N)     orow[c]     = lo;
            if (c + 1 < N) orow[c + 1] = hi;
        }
    }
}

// ============ init-time 64x64 ping-pong GEMM (tables)
__global__ __launch_bounds__(256) void gemm64(
    const float* __restrict__ A, const float* __restrict__ W,
    const float* __restrict__ bias, float* __restrict__ out,
    int M, int N, int ldout, float scale)
{
    __shared__ __align__(16) float As[2][16][68];
    __shared__ __align__(16) float Bs[2][16][68];
    int col0 = blockIdx.x * 64, row0 = blockIdx.y * 64;
    int t = threadIdx.x, tx = t & 15, ty = t >> 4;
    ull acc[4][2];
#pragma unroll
    for (int i = 0; i < 4; i++) { acc[i][0] = 0ULL; acc[i][1] = 0ULL; }

    int am = t >> 2, akg = t & 3;
    int gmA = row0 + am, gnB = col0 + am;

    float4 ra = (gmA < M) ? *(const float4*)&A[(size_t)gmA * 512 + akg * 4]
                          : make_float4(0.f,0.f,0.f,0.f);
    float4 rb = (gnB < N) ? *(const float4*)&W[(size_t)gnB * 512 + akg * 4]
                          : make_float4(0.f,0.f,0.f,0.f);
    As[0][akg*4+0][am] = ra.x; As[0][akg*4+1][am] = ra.y;
    As[0][akg*4+2][am] = ra.z; As[0][akg*4+3][am] = ra.w;
    Bs[0][akg*4+0][am] = rb.x; Bs[0][akg*4+1][am] = rb.y;
    Bs[0][akg*4+2][am] = rb.z; Bs[0][akg*4+3][am] = rb.w;
    __syncthreads();

    for (int it = 0; it < 32; it++) {
        int cur = it & 1;
        if (it < 31) {
            int k0 = (it + 1) * 16;
            ra = (gmA < M) ? *(const float4*)&A[(size_t)gmA * 512 + k0 + akg * 4]
                           : make_float4(0.f,0.f,0.f,0.f);
            rb = (gnB < N) ? *(const float4*)&W[(size_t)gnB * 512 + k0 + akg * 4]
                           : make_float4(0.f,0.f,0.f,0.f);
        }
#pragma unroll
        for (int kk = 0; kk < 16; kk++) {
            ull b0 = *(const ull*)&Bs[cur][kk][tx*4];
            ull b1 = *(const ull*)&Bs[cur][kk][tx*4+2];
            float4 a = *(const float4*)&As[cur][kk][ty*4];
            ull a0=pack2(a.x,a.x), a1=pack2(a.y,a.y);
            ull a2=pack2(a.z,a.z), a3=pack2(a.w,a.w);
            FMA2(acc[0][0],a0,b0); FMA2(acc[0][1],a0,b1);
            FMA2(acc[1][0],a1,b0); FMA2(acc[1][1],a1,b1);
            FMA2(acc[2][0],a2,b0); FMA2(acc[2][1],a2,b1);
            FMA2(acc[3][0],a3,b0); FMA2(acc[3][1],a3,b1);
        }
        if (it < 31) {
            int nxt = 1 - cur;
            As[nxt][akg*4+0][am] = ra.x; As[nxt][akg*4+1][am] = ra.y;
            As[nxt][akg*4+2][am] = ra.z; As[nxt][akg*4+3][am] = ra.w;
            Bs[nxt][akg*4+0][am] = rb.x; Bs[nxt][akg*4+1][am] = rb.y;
            Bs[nxt][akg*4+2][am] = rb.z; Bs[nxt][akg*4+3][am] = rb.w;
        }
        __syncthreads();
    }
#pragma unroll
    for (int i = 0; i < 4; i++) {
        int gm = row0 + ty * 4 + i;
        if (gm >= M) continue;
        float* orow = out + (size_t)gm * (size_t)ldout;
#pragma unroll
        for (int j = 0; j < 2; j++) {
            float lo, hi;
            unpack2(acc[i][j], lo, hi);
            int c = col0 + tx * 4 + j * 2;
            if (c < N)     orow[c]     = lo * scale + (bias ? bias[c]     : 0.f);
            if (c + 1 < N) orow[c + 1] = hi * scale + (bias ? bias[c + 1] : 0.f);
        }
    }
}

// ============ KW = Krel @ Wq (B K-row-major)
__global__ __launch_bounds__(256) void k_gemm_kn(
    const float* __restrict__ A, const float* __restrict__ B,
    float* __restrict__ out, int M, int N, int ldb)
{
    __shared__ __align__(16) float As[16][68];
    __shared__ __align__(16) float Bs[16][68];
    int col0 = blockIdx.x * 64, row0 = blockIdx.y * 64;
    int t = threadIdx.x, tx = t & 15, ty = t >> 4;
    ull acc[4][2];
#pragma unroll
    for (int i = 0; i < 4; i++) { acc[i][0] = 0ULL; acc[i][1] = 0ULL; }

    int am = t >> 2, akg = t & 3;
    int gmA = row0 + am;
    int kkB = t >> 4, ngB = t & 15;

    for (int k0 = 0; k0 < 512; k0 += 16) {
        float4 ra = (gmA < M) ? *(const float4*)&A[(size_t)gmA*512 + k0 + akg*4]
                              : make_float4(0.f,0.f,0.f,0.f);
        float4 rb = *(const float4*)&B[(size_t)(k0 + kkB) * ldb + col0 + ngB * 4];
        As[akg*4+0][am] = ra.x; As[akg*4+1][am] = ra.y;
        As[akg*4+2][am] = ra.z; As[akg*4+3][am] = ra.w;
        Bs[kkB][ngB*4+0] = rb.x; Bs[kkB][ngB*4+1] = rb.y;
        Bs[kkB][ngB*4+2] = rb.z; Bs[kkB][ngB*4+3] = rb.w;
        __syncthreads();
#pragma unroll
        for (int kk = 0; kk < 16; kk++) {
            ull b0 = *(const ull*)&Bs[kk][tx*4];
            ull b1 = *(const ull*)&Bs[kk][tx*4+2];
            float4 a = *(const float4*)&As[kk][ty*4];
            ull a0=pack2(a.x,a.x), a1=pack2(a.y,a.y);
            ull a2=pack2(a.z,a.z), a3=pack2(a.w,a.w);
            FMA2(acc[0][0],a0,b0); FMA2(acc[0][1],a0,b1);
            FMA2(acc[1][0],a1,b0); FMA2(acc[1][1],a1,b1);
            FMA2(acc[2][0],a2,b0); FMA2(acc[2][1],a2,b1);
            FMA2(acc[3][0],a3,b0); FMA2(acc[3][1],a3,b1);
        }
        __syncthreads();
    }
#pragma unroll
    for (int i = 0; i < 4; i++) {
        int gm = row0 + ty * 4 + i;
        if (gm >= M) continue;
#pragma unroll
        for (int j = 0; j < 2; j++) {
            float lo, hi;
            unpack2(acc[i][j], lo, hi);
            int c = col0 + tx * 4 + j * 2;
            if (c < N)     out[(size_t)gm * N + c]     = lo;
            if (c + 1 < N) out[(size_t)gm * N + c + 1] = hi;
        }
    }
}

// ============ AT[m][n] = sum_k Wk[k][m] * Wq[k][n]
__global__ __launch_bounds__(256) void k_gemm_tn(
    const float* __restrict__ P, const float* __restrict__ Q, float* __restrict__ out)
{
    __shared__ __align__(16) float As[16][68];
    __shared__ __align__(16) float Bs[16][68];
    int col0 = blockIdx.x * 64, row0 = blockIdx.y * 64;
    int t = threadIdx.x, tx = t & 15, ty = t >> 4;
    ull acc[4][2];
#pragma unroll
    for (int i = 0; i < 4; i++) { acc[i][0] = 0ULL; acc[i][1] = 0ULL; }
    int kk0 = t >> 4, g = t & 15;

    for (int k0 = 0; k0 < 512; k0 += 16) {
        float4 ra = *(const float4*)&P[(size_t)(k0 + kk0) * 512 + row0 + g * 4];
        float4 rb = *(const float4*)&Q[(size_t)(k0 + kk0) * 512 + col0 + g * 4];
        As[kk0][g*4+0] = ra.x; As[kk0][g*4+1] = ra.y;
        As[kk0][g*4+2] = ra.z; As[kk0][g*4+3] = ra.w;
        Bs[kk0][g*4+0] = rb.x; Bs[kk0][g*4+1] = rb.y;
        Bs[kk0][g*4+2] = rb.z; Bs[kk0][g*4+3] = rb.w;
        __syncthreads();
#pragma unroll
        for (int kk = 0; kk < 16; kk++) {
            ull b0 = *(const ull*)&Bs[kk][tx*4];
            ull b1 = *(const ull*)&Bs[kk][tx*4+2];
            float4 a = *(const float4*)&As[kk][ty*4];
            ull a0=pack2(a.x,a.x), a1=pack2(a.y,a.y);
            ull a2=pack2(a.z,a.z), a3=pack2(a.w,a.w);
            FMA2(acc[0][0],a0,b0); FMA2(acc[0][1],a0,b1);
            FMA2(acc[1][0],a1,b0); FMA2(acc[1][1],a1,b1);
            FMA2(acc[2][0],a2,b0); FMA2(acc[2][1],a2,b1);
            FMA2(acc[3][0],a3,b0); FMA2(acc[3][1],a3,b1);
        }
        __syncthreads();
    }
#pragma unroll
    for (int i = 0; i < 4; i++) {
        int gm = row0 + ty * 4 + i;
#pragma unroll
        for (int j = 0; j < 2; j++) {
            float lo, hi;
            unpack2(acc[i][j], lo, hi);
            int c = col0 + tx * 4 + j * 2;
            out[(size_t)gm * 512 + c]     = lo;
            out[(size_t)gm * 512 + c + 1] = hi;
        }
    }
}

__global__ void k_wc(const float* __restrict__ Wq, const float* __restrict__ bq,
                     const float* __restrict__ Wk, const float* __restrict__ bk) {
    __shared__ float red[256];
    int t = threadIdx.x;
    int i = blockIdx.x * 256 + t;
    float acc = 0.f;
    for (int n = 0; n < EE; n++)
        acc += Wq[(size_t)n * EE + i] * bk[n] + Wk[(size_t)n * EE + i] * bq[n];
    g_wvec[i] = acc;
    if (blockIdx.x == 0) {
        float p = 0.f;
        for (int n = t; n < EE; n += 256) p += bq[n] * bk[n];
        red[t] = p; __syncthreads();
        for (int s = 128; s > 0; s >>= 1) { if (t < s) red[t] += red[t + s]; __syncthreads(); }
        if (t == 0) g_c0[0] = red[0];
    }
}

__global__ void k_h1emb(const float* __restrict__ b_hh) {
    int tk = blockIdx.x;
    const float* gi = &GI_emb[(size_t)tk * G3];
    for (int e = threadIdx.x; e < EE; e += blockDim.x) {
        float r = sigmf(gi[e] + b_hh[e]);
        float z = sigmf(gi[EE + e] + b_hh[EE + e]);
        float n = tanhf(gi[2 * EE + e] + r * b_hh[2 * EE + e]);
        H1_emb[(size_t)tk * EE + e] = (1.f - z) * n;
    }
}

__global__ void k_cinit(const float* __restrict__ bq) {
    int r = blockIdx.x * 8 + (threadIdx.x >> 5);
    int lane = threadIdx.x & 31;
    if (r >= RR) return;
    float s = 0.f;
    for (int e = lane; e < EE; e += 32) s += bq[e] * g_Krel[(size_t)r * EE + e];
#pragma unroll
    for (int off = 16; off > 0; off >>= 1) s += __shfl_down_sync(0xffffffffu, s, off);
    if (lane == 0) g_cs[r] = NSCALE * s;
}

// =================== round-phase kernels ===================

__device__ __forceinline__ float pair_elem(const float* gi, const float* gh,
                                           const float* h1, int e) {
    float r = sigmf(gi[e] + gh[e]);
    float z = sigmf(gi[EE + e] + gh[EE + e]);
    float n = tanhf(gi[2 * EE + e] + r * gh[2 * EE + e]);
    return (1.f - z) * n + z * h1[e];
}

__global__ void k_pairsel(const float* __restrict__ wfc, const float* __restrict__ bfc,
                          const float* __restrict__ b_hh,
                          int npairs, int zloss, float* __restrict__ loss_out, int first) {
    int b = blockIdx.x, t = threadIdx.x;
    int w = t >> 5, lane = t & 31;
    __shared__ int sord[SS];
    __shared__ float sps[SS];
    __shared__ int sbestj;

    // finalize previous round's ghh partials into g_ghh[b][prev_dslot]
    if (!first) {
        int slot = g_dslot[b];
        float* orow = &g_ghh[((size_t)b * SS + slot) * G3];
        const float* gA = &g_gh0[(size_t)b * G3];
        const float* gB = &g_gh1[(size_t)b * G3];
        for (int e = t; e < G3; e += 256) orow[e] = gA[e] + gB[e] + b_hh[e];
        __syncthreads();
    }

    if (t < SS) {
        sord[t] = g_ord[b * SS + t];
        sps[t]  = g_pscore[b * SS + t];
    }
    int prev_sel = g_sel[b];
    __syncthreads();

    int j0 = -1, j1 = -1;
    if (first) {
        j0 = w;  j1 = w + 8;
        if (j0 >= npairs) j0 = -1;
        if (j1 >= npairs) j1 = -1;
    } else {
        int cnt = 0, jj[2];
        if (prev_sel - 1 >= 0 && prev_sel - 1 < npairs) jj[cnt++] = prev_sel - 1;
        if (prev_sel >= 0 && prev_sel < npairs)         jj[cnt++] = prev_sel;
        if (w < cnt) j0 = jj[w];
    }
#pragma unroll
    for (int rep = 0; rep < 2; rep++) {
        int j = (rep == 0) ? j0 : j1;
        if (j >= 0) {
            const float* gi = p_gi(b, sord[j + 1]);
            const float* gh = p_ghh(b, sord[j]);
            const float* h1 = p_h1(b, sord[j]);
            float s = 0.f;
            for (int e = lane; e < EE; e += 32)
                s += pair_elem(gi, gh, h1, e) * wfc[e];
#pragma unroll
            for (int off = 16; off > 0; off >>= 1)
                s += __shfl_down_sync(0xffffffffu, s, off);
            if (lane == 0) {
                float sc = sigmf(s + bfc[0]);
                sps[j] = sc;
                g_pscore[b * SS + j] = sc;
            }
        }
    }
    __syncthreads();

    if (t == 0) {
        int bj = 0; float bs = sps[0];
        for (int j = 1; j < npairs; j++)
            if (sps[j] > bs) { bs = sps[j]; bj = j; }
        sbestj = bj;
        g_sel[b] = bj;
        if (zloss >= 0) loss_out[b * SS + zloss] = 0.f;
    }
    __syncthreads();
    int j = sbestj;
    const float* gi = p_gi(b, sord[j + 1]);
    const float* gh = p_ghh(b, sord[j]);
    const float* h1 = p_h1(b, sord[j]);
    for (int e = t; e < EE; e += 256)
        g_pair[(size_t)b * EE + e] = pair_elem(gi, gh, h1, e);
}

__device__ __forceinline__ float bsum(float v, float* red, int t) {
    red[t] = v; __syncthreads();
    for (int s = 128; s > 0; s >>= 1) { if (t < s) red[t] += red[t + s]; __syncthreads(); }
    return red[0];
}
__device__ __forceinline__ float bmax(float v, float* red, int t) {
    red[t] = v; __syncthreads();
    for (int s = 128; s > 0; s >>= 1) { if (t < s) red[t] = fmaxf(red[t], red[t + s]); __syncthreads(); }
    return red[0];
}

__global__ void k_softmax(int lossidx, int L, int do_book,
                          float* __restrict__ loss_out, float* __restrict__ scores_out) {
    int b = blockIdx.x, t = threadIdx.x;
    __shared__ float red[256];
    const float* pp  = &g_pair[(size_t)b * EE];
    const float* tv0 = &g_tv0[(size_t)b * EE];
    const float* tv1 = &g_tv1[(size_t)b * EE];
    const float* s0  = &g_sc0[(size_t)b * RR];
    const float* s1  = &g_sc1[(size_t)b * RR];

    float part = 0.f;
    for (int e = t; e < EE; e += 256)
        part += (tv0[e] + tv1[e] + g_wvec[e]) * pp[e];
    float c1000 = (bsum(part, red, t) + g_c0[0]) * NSCALE;
    __syncthreads();

    float m = -3.4e38f;
    for (int k = t; k <= RR; k += 256) {
        float v = (k < RR) ? ((s0[k] + s1[k]) * NSCALE + g_cs[k]) : c1000;
        m = fmaxf(m, v);
    }
    m = bmax(m, red, t);
    __syncthreads();

    float se = 0.f, sv = 0.f;
    for (int k = t; k <= RR; k += 256) {
        float raw = (k < RR) ? ((s0[k] + s1[k]) * NSCALE + g_cs[k]) : c1000;
        float v = raw - m;
        float ev = expf(v);
        se += ev; sv += ev * v;
    }
    float Z = bsum(se, red, t);
    __syncthreads();
    float S2 = bsum(sv, red, t);
    if (t == 0) loss_out[b * SS + lossidx] = logf(Z) - S2 / Z;

    float* pr = &g_prob[(size_t)b * (RR + 1)];
    for (int k = t; k <= RR; k += 256) {
        float raw = (k < RR) ? ((s0[k] + s1[k]) * NSCALE + g_cs[k]) : c1000;
        pr[k] = expf(raw - m) / Z;
        if (scores_out) scores_out[(size_t)b * (RR + 1) + k] = raw;
    }
    if (t == 0 && do_book) {
        int sel = g_sel[b];
        int* ord = &g_ord[b * SS];
        float* ps = &g_pscore[b * SS];
        int slot = ord[sel];
        g_dslot[b] = slot;
        g_src[b * SS + slot] = -1;
        for (int i = sel + 1; i < L - 1; i++) { ord[i] = ord[i + 1]; ps[i] = ps[i + 1]; }
    }
}

// finalize gi (sum 4 gimix partials + pp*(giP partials + b_ih)), scatter, compute h1
__global__ void k_h1fin(const float* __restrict__ b_ih, const float* __restrict__ b_hh) {
    __shared__ __align__(16) float sgi[G3];
    int b = blockIdx.x, t = threadIdx.x;
    int slot = g_dslot[b];
    float pp = g_prob[(size_t)b * (RR + 1) + RR];
    float* orow = &g_gi[((size_t)b * SS + slot) * G3];
    const float* m0 = &g_gm4[0][(size_t)b * G3];
    const float* m1 = &g_gm4[1][(size_t)b * G3];
    const float* m2 = &g_gm4[2][(size_t)b * G3];
    const float* m3 = &g_gm4[3][(size_t)b * G3];
    const float* p0 = &g_gp0[(size_t)b * G3];
    const float* p1 = &g_gp1[(size_t)b * G3];
    for (int e = t; e < G3; e += 256) {
        float v = m0[e] + m1[e] + m2[e] + m3[e] + pp * (p0[e] + p1[e] + b_ih[e]);
        sgi[e] = v;
        orow[e] = v;
    }
    __syncthreads();
    for (int e = t; e < EE; e += 256) {
        float r = sigmf(sgi[e] + b_hh[e]);
        float z = sigmf(sgi[EE + e] + b_hh[EE + e]);
        float n = tanhf(sgi[2 * EE + e] + r * b_hh[2 * EE + e]);
        float h = (1.f - z) * n;
        g_h1[((size_t)b * SS + slot) * EE + e] = h;
        g_newh1[(size_t)b * EE + e] = h;
    }
}

// ---------------- host ----------------
extern "C" void kernel_launch(void* const* d_in, const int* in_sizes, int n_in,
                              void* d_out, int out_size) {
    const int*   tokens = (const int*)  d_in[0];
    const float* emb    = (const float*)d_in[1];
    const float* W_ih   = (const float*)d_in[2];
    const float* W_hh   = (const float*)d_in[3];
    const float* b_ih   = (const float*)d_in[4];
    const float* b_hh   = (const float*)d_in[5];
    const float* w_fc   = (const float*)d_in[6];
    const float* b_fc   = (const float*)d_in[7];
    const float* Wq     = (const float*)d_in[8];
    const float* bq     = (const float*)d_in[9];
    const float* Wk     = (const float*)d_in[10];
    const float* bk     = (const float*)d_in[11];

    float* out_scores = (float*)d_out;                         // 128 x 1001
    float* out_loss   = (float*)d_out + (size_t)BB * (RR + 1); // 128 x 16

    float *GI, *H1, *GHH, *Krel, *KW, *AT;
    cudaGetSymbolAddress((void**)&GI, GI_emb);
    cudaGetSymbolAddress((void**)&H1, H1_emb);
    cudaGetSymbolAddress((void**)&GHH, GHH_emb);
    cudaGetSymbolAddress((void**)&Krel, g_Krel);
    cudaGetSymbolAddress((void**)&KW, g_KW);
    cudaGetSymbolAddress((void**)&AT, g_AT);

    // ---- init (once per call) ----
    k_init<<<BB, 32>>>(tokens);
    gemm64<<<dim3(24, 16), 256>>>(emb, W_ih, b_ih, GI, RR, G3, G3, 1.f);
    k_h1emb<<<RR, 256>>>(b_hh);
    gemm64<<<dim3(24, 16), 256>>>(H1, W_hh, b_hh, GHH, RR, G3, G3, 1.f);
    gemm64<<<dim3(8, 16), 256>>>(emb, Wk, bk, Krel, RR, EE, EE, 1.f);
    k_gemm_kn<<<dim3(8, 16), 256>>>(Krel, Wq, KW, RR, EE, EE);
    k_cinit<<<125, 256>>>(bq);
    k_gemm_tn<<<dim3(8, 8), 256>>>(Wk, Wq, AT);
    k_wc<<<2, 256>>>(Wq, bq, Wk, bk);

    // ---- 14 merge rounds ----
    for (int i = 0; i < 14; i++) {
        int L = SS - i;
        k_pairsel<<<BB, 256>>>(w_fc, b_fc, b_hh, L - 1, -1, out_loss, i == 0);
        k_mm<<<dim3(48, 2, 2), 256>>>(PH_BGA, W_ih, W_hh);   // scores + tvec + giP
        k_softmax<<<BB, 256>>>(i, L, 1, out_loss, NULL);
        k_mm<<<dim3(24, 2, 4), 256>>>(PH_GIMIX, W_ih, W_hh); // prob @ GI_emb partials
        k_h1fin<<<BB, 256>>>(b_ih, b_hh);
        k_mm<<<dim3(24, 2, 2), 256>>>(PH_GHH, W_ih, W_hh);   // newh1 @ W_hh partials
    }
    // ---- final round (L=2) + output attention ----
    k_pairsel<<<BB, 256>>>(w_fc, b_fc, b_hh, 1, 14, out_loss, 0);
    k_mm<<<dim3(24, 2, 2), 256>>>(PH_BGA, W_ih, W_hh);       // scores + tvec only
    k_softmax<<<BB, 256>>>(15, 0, 0, out_loss, out_scores);
}

// round 11
// speedup vs baseline: 1.5052x; 1.1121x over previous
#include <cuda_runtime.h>
#include <math.h>

#define BB 128
#define SS 16
#define EE 512
#define RR 1000
#define G3 1536
#define NSCALE 0.04419417382415922f

// ---- device scratch (static, no allocations) ----
__device__ float GI_emb[RR * G3];
__device__ float H1_emb[RR * EE];
__device__ float GHH_emb[RR * G3];
__device__ float g_Krel[RR * EE];
__device__ float g_KW[RR * EE];
__device__ float g_cs[RR];
__device__ float g_AT[EE * EE];
__device__ float g_wvec[EE];
__device__ float g_c0[1];

__device__ float g_gi [BB * SS * G3];
__device__ float g_h1 [BB * SS * EE];
__device__ float g_ghh[BB * SS * G3];

__device__ int   g_src [BB * SS];
__device__ int   g_ord [BB * SS];
__device__ int   g_sel [BB];
__device__ int   g_dslot[BB];
__device__ float g_pscore[BB * SS];

__device__ float g_pair [BB * EE];
__device__ float g_newh1[BB * EE];
__device__ float g_probp[BB * 1024];   // padded probs, [1000..1023] = 0
__device__ float g_pp[BB];             // prob of the pair key

// split-K partial buffers
__device__ float g_sc0[BB * RR];
__device__ float g_sc1[BB * RR];
__device__ float g_tv0[BB * EE];
__device__ float g_tv1[BB * EE];
__device__ float g_gp0[BB * G3];
__device__ float g_gp1[BB * G3];
__device__ float g_gm4[4][BB * G3];
__device__ float g_gh[4][BB * G3];

typedef unsigned long long ull;
__device__ __forceinline__ ull pack2(float lo, float hi) {
    ull r; asm("mov.b64 %0, {%1, %2};" : "=l"(r) : "f"(lo), "f"(hi)); return r;
}
__device__ __forceinline__ void unpack2(ull v, float& lo, float& hi) {
    asm("mov.b64 {%0, %1}, %2;" : "=f"(lo), "=f"(hi) : "l"(v));
}
#define FMA2(acc, a, b) asm("fma.rn.f32x2 %0, %1, %2, %0;" : "+l"(acc) : "l"(a), "l"(b))

__device__ __forceinline__ float sigmf(float x) { return 1.0f / (1.0f + expf(-x)); }

__device__ __forceinline__ const float* p_gi(int b, int s) {
    int src = g_src[b * SS + s];
    return (src >= 0) ? &GI_emb[(size_t)src * G3] : &g_gi[((size_t)b * SS + s) * G3];
}
__device__ __forceinline__ const float* p_ghh(int b, int s) {
    int src = g_src[b * SS + s];
    return (src >= 0) ? &GHH_emb[(size_t)src * G3] : &g_ghh[((size_t)b * SS + s) * G3];
}
__device__ __forceinline__ const float* p_h1(int b, int s) {
    int src = g_src[b * SS + s];
    return (src >= 0) ? &H1_emb[(size_t)src * EE] : &g_h1[((size_t)b * SS + s) * EE];
}

__global__ void k_init(const int* __restrict__ tokens) {
    int b = blockIdx.x, t = threadIdx.x;
    if (t < SS) {
        g_ord[b * SS + t] = t;
        g_src[b * SS + t] = tokens[b * SS + t];
    }
}

// ======================================================================
// Per-round GEMM: 64x64 tile, 4x4 f32x2 reg tile, dup-A smem, conflict-free.
// Split-K partials, raw output (bias/scale in consumers).
// ======================================================================
#define PH_BGA   0   // A=g_pair : xt<16 scores(KW), xt<24 tvec(AT);  z = K-slice (2)
#define PH_GIMIX 1   // z<4: prob@GI_emb slices;  z in {4,5}: giP = pair@W_ih slices
#define PH_GHH   2   // A=g_newh1, B=W_hh, z = K-slice (4, 8 iters)

__global__ __launch_bounds__(256) void k_mm(int phase,
    const float* __restrict__ W_ih, const float* __restrict__ W_hh)
{
    __shared__ __align__(16) float shA[16][136];
    __shared__ __align__(16) float shB[16][68];
    int t = threadIdx.x, tx = t & 15, ty = t >> 4;
    int xt = blockIdx.x, yt = blockIdx.y, ks = blockIdx.z;

    const float* A; int lda; const float* W; float* out; int N, wld;
    int kn = 0, kb, NIT = 16, Kmax = 1 << 30;
    if (phase == PH_BGA) {
        A = g_pair; lda = 512; wld = 512; kb = ks * 256;
        if (xt < 16) { W = g_KW; out = ks ? g_sc1 : g_sc0; N = RR; }
        else         { W = g_AT; out = ks ? g_tv1 : g_tv0; N = EE; xt -= 16; }
    } else if (phase == PH_GIMIX) {
        if (ks < 4) {
            A = g_probp; lda = 1024; W = GI_emb; wld = G3;
            out = g_gm4[ks]; N = G3; kn = 1; kb = ks * 256; Kmax = RR;
        } else {
            A = g_pair; lda = 512; W = W_ih; wld = 512;
            out = (ks == 5) ? g_gp1 : g_gp0; N = G3; kb = (ks - 4) * 256;
        }
    } else {
        A = g_newh1; lda = 512; W = W_hh; wld = 512;
        out = g_gh[ks]; N = G3; kb = ks * 128; NIT = 8;
    }
    int col0 = xt * 64, row0 = yt * 64;

    ull acc[4][2];
#pragma unroll
    for (int i = 0; i < 4; i++) { acc[i][0] = 0ULL; acc[i][1] = 0ULL; }

    int am = t >> 2, akg = t & 3;
    int gmA = row0 + am;
    int bn = t >> 2, bkg = t & 3;       // kn==0 (W is N-row-major)
    int kkB = t >> 4, ngB = t & 15;     // kn==1 (W is K-row-major)

    float4 ra = *(const float4*)&A[(size_t)gmA * lda + kb + akg * 4];
    float4 rb;
    if (kn == 0) {
        int gn = col0 + bn;
        rb = (gn < N) ? *(const float4*)&W[(size_t)gn * wld + kb + bkg * 4]
                      : make_float4(0.f, 0.f, 0.f, 0.f);
    } else {
        int k = kb + kkB;
        rb = (k < Kmax) ? *(const float4*)&W[(size_t)k * wld + col0 + ngB * 4]
                        : make_float4(0.f, 0.f, 0.f, 0.f);
    }

    for (int it = 0; it < NIT; it++) {
        *(ull*)&shA[akg * 4 + 0][am * 2] = pack2(ra.x, ra.x);
        *(ull*)&shA[akg * 4 + 1][am * 2] = pack2(ra.y, ra.y);
        *(ull*)&shA[akg * 4 + 2][am * 2] = pack2(ra.z, ra.z);
        *(ull*)&shA[akg * 4 + 3][am * 2] = pack2(ra.w, ra.w);
        if (kn == 0) {
            shB[bkg*4+0][bn] = rb.x; shB[bkg*4+1][bn] = rb.y;
            shB[bkg*4+2][bn] = rb.z; shB[bkg*4+3][bn] = rb.w;
        } else {
            *(float4*)&shB[kkB][ngB * 4] = rb;
        }
        __syncthreads();
        if (it < NIT - 1) {
            int k0 = kb + (it + 1) * 16;
            ra = *(const float4*)&A[(size_t)gmA * lda + k0 + akg * 4];
            if (kn == 0) {
                int gn = col0 + bn;
                rb = (gn < N) ? *(const float4*)&W[(size_t)gn * wld + k0 + bkg * 4]
                              : make_float4(0.f, 0.f, 0.f, 0.f);
            } else {
                int k = k0 + kkB;
                rb = (k < Kmax) ? *(const float4*)&W[(size_t)k * wld + col0 + ngB * 4]
                                : make_float4(0.f, 0.f, 0.f, 0.f);
            }
        }
#pragma unroll
        for (int kk = 0; kk < 16; kk++) {
            ulonglong2 bv  = *(const ulonglong2*)&shB[kk][tx * 4];
            ulonglong2 a01 = *(const ulonglong2*)&shA[kk][ty * 8];
            ulonglong2 a23 = *(const ulonglong2*)&shA[kk][ty * 8 + 4];
            FMA2(acc[0][0], a01.x, bv.x); FMA2(acc[0][1], a01.x, bv.y);
            FMA2(acc[1][0], a01.y, bv.x); FMA2(acc[1][1], a01.y, bv.y);
            FMA2(acc[2][0], a23.x, bv.x); FMA2(acc[2][1], a23.x, bv.y);
            FMA2(acc[3][0], a23.y, bv.x); FMA2(acc[3][1], a23.y, bv.y);
        }
        __syncthreads();
    }
#pragma unroll
    for (int i = 0; i < 4; i++) {
        int gm = row0 + ty * 4 + i;
        float* orow = out + (size_t)gm * N;
#pragma unroll
        for (int j = 0; j < 2; j++) {
            float lo, hi;
            unpack2(acc[i][j], lo, hi);
            int c = col0 + tx * 4 + j * 2;
            if (c < N)     orow[c]     = lo;
            if (c + 1 < N) orow[c + 1] = hi;
        }
    }
}

// ============ init table GEMM: out = A@W^T*scale + bias (dup-A core, M guard)
__global__ __launch_bounds__(256) void k_tab(
    const float* __restrict__ A, const float* __restrict__ W,
    const float* __restrict__ bias, float* __restrict__ out,
    int M, int N, int ldout, float scale)
{
    __shared__ __align__(16) float shA[16][136];
    __shared__ __align__(16) float shB[16][68];
    int t = threadIdx.x, tx = t & 15, ty = t >> 4;
    int col0 = blockIdx.x * 64, row0 = blockIdx.y * 64;

    ull acc[4][2];
#pragma unroll
    for (int i = 0; i < 4; i++) { acc[i][0] = 0ULL; acc[i][1] = 0ULL; }

    int am = t >> 2, akg = t & 3;
    int gmA = row0 + am;
    int bn = t >> 2, bkg = t & 3;
    int gnB = col0 + bn;

    float4 ra = (gmA < M) ? *(const float4*)&A[(size_t)gmA * 512 + akg * 4]
                          : make_float4(0.f, 0.f, 0.f, 0.f);
    float4 rb = (gnB < N) ? *(const float4*)&W[(size_t)gnB * 512 + bkg * 4]
                          : make_float4(0.f, 0.f, 0.f, 0.f);

    for (int it = 0; it < 32; it++) {
        *(ull*)&shA[akg * 4 + 0][am * 2] = pack2(ra.x, ra.x);
        *(ull*)&shA[akg * 4 + 1][am * 2] = pack2(ra.y, ra.y);
        *(ull*)&shA[akg * 4 + 2][am * 2] = pack2(ra.z, ra.z);
        *(ull*)&shA[akg * 4 + 3][am * 2] = pack2(ra.w, ra.w);
        shB[bkg*4+0][bn] = rb.x; shB[bkg*4+1][bn] = rb.y;
        shB[bkg*4+2][bn] = rb.z; shB[bkg*4+3][bn] = rb.w;
        __syncthreads();
        if (it < 31) {
            int k0 = (it + 1) * 16;
            ra = (gmA < M) ? *(const float4*)&A[(size_t)gmA * 512 + k0 + akg * 4]
                           : make_float4(0.f, 0.f, 0.f, 0.f);
            rb = (gnB < N) ? *(const float4*)&W[(size_t)gnB * 512 + k0 + bkg * 4]
                           : make_float4(0.f, 0.f, 0.f, 0.f);
        }
#pragma unroll
        for (int kk = 0; kk < 16; kk++) {
            ulonglong2 bv  = *(const ulonglong2*)&shB[kk][tx * 4];
            ulonglong2 a01 = *(const ulonglong2*)&shA[kk][ty * 8];
            ulonglong2 a23 = *(const ulonglong2*)&shA[kk][ty * 8 + 4];
            FMA2(acc[0][0], a01.x, bv.x); FMA2(acc[0][1], a01.x, bv.y);
            FMA2(acc[1][0], a01.y, bv.x); FMA2(acc[1][1], a01.y, bv.y);
            FMA2(acc[2][0], a23.x, bv.x); FMA2(acc[2][1], a23.x, bv.y);
            FMA2(acc[3][0], a23.y, bv.x); FMA2(acc[3][1], a23.y, bv.y);
        }
        __syncthreads();
    }
#pragma unroll
    for (int i = 0; i < 4; i++) {
        int gm = row0 + ty * 4 + i;
        if (gm >= M) continue;
        float* orow = out + (size_t)gm * (size_t)ldout;
#pragma unroll
        for (int j = 0; j < 2; j++) {
            float lo, hi;
            unpack2(acc[i][j], lo, hi);
            int c = col0 + tx * 4 + j * 2;
            if (c < N)     orow[c]     = lo * scale + (bias ? bias[c]     : 0.f);
            if (c + 1 < N) orow[c + 1] = hi * scale + (bias ? bias[c + 1] : 0.f);
        }
    }
}

// ============ KW = Krel @ Wq (B K-row-major)
__global__ __launch_bounds__(256) void k_gemm_kn(
    const float* __restrict__ A, const float* __restrict__ B,
    float* __restrict__ out, int M, int N, int ldb)
{
    __shared__ __align__(16) float As[16][68];
    __shared__ __align__(16) float Bs[16][68];
    int col0 = blockIdx.x * 64, row0 = blockIdx.y * 64;
    int t = threadIdx.x, tx = t & 15, ty = t >> 4;
    ull acc[4][2];
#pragma unroll
    for (int i = 0; i < 4; i++) { acc[i][0] = 0ULL; acc[i][1] = 0ULL; }

    int am = t >> 2, akg = t & 3;
    int gmA = row0 + am;
    int kkB = t >> 4, ngB = t & 15;

    for (int k0 = 0; k0 < 512; k0 += 16) {
        float4 ra = (gmA < M) ? *(const float4*)&A[(size_t)gmA*512 + k0 + akg*4]
                              : make_float4(0.f,0.f,0.f,0.f);
        float4 rb = *(const float4*)&B[(size_t)(k0 + kkB) * ldb + col0 + ngB * 4];
        As[akg*4+0][am] = ra.x; As[akg*4+1][am] = ra.y;
        As[akg*4+2][am] = ra.z; As[akg*4+3][am] = ra.w;
        Bs[kkB][ngB*4+0] = rb.x; Bs[kkB][ngB*4+1] = rb.y;
        Bs[kkB][ngB*4+2] = rb.z; Bs[kkB][ngB*4+3] = rb.w;
        __syncthreads();
#pragma unroll
        for (int kk = 0; kk < 16; kk++) {
            ull b0 = *(const ull*)&Bs[kk][tx*4];
            ull b1 = *(const ull*)&Bs[kk][tx*4+2];
            float4 a = *(const float4*)&As[kk][ty*4];
            ull a0=pack2(a.x,a.x), a1=pack2(a.y,a.y);
            ull a2=pack2(a.z,a.z), a3=pack2(a.w,a.w);
            FMA2(acc[0][0],a0,b0); FMA2(acc[0][1],a0,b1);
            FMA2(acc[1][0],a1,b0); FMA2(acc[1][1],a1,b1);
            FMA2(acc[2][0],a2,b0); FMA2(acc[2][1],a2,b1);
            FMA2(acc[3][0],a3,b0); FMA2(acc[3][1],a3,b1);
        }
        __syncthreads();
    }
#pragma unroll
    for (int i = 0; i < 4; i++) {
        int gm = row0 + ty * 4 + i;
        if (gm >= M) continue;
#pragma unroll
        for (int j = 0; j < 2; j++) {
            float lo, hi;
            unpack2(acc[i][j], lo, hi);
            int c = col0 + tx * 4 + j * 2;
            if (c < N)     out[(size_t)gm * N + c]     = lo;
            if (c + 1 < N) out[(size_t)gm * N + c + 1] = hi;
        }
    }
}

// ============ AT[m][n] = sum_k Wk[k][m] * Wq[k][n]
__global__ __launch_bounds__(256) void k_gemm_tn(
    const float* __restrict__ P, const float* __restrict__ Q, float* __restrict__ out)
{
    __shared__ __align__(16) float As[16][68];
    __shared__ __align__(16) float Bs[16][68];
    int col0 = blockIdx.x * 64, row0 = blockIdx.y * 64;
    int t = threadIdx.x, tx = t & 15, ty = t >> 4;
    ull acc[4][2];
#pragma unroll
    for (int i = 0; i < 4; i++) { acc[i][0] = 0ULL; acc[i][1] = 0ULL; }
    int kk0 = t >> 4, g = t & 15;

    for (int k0 = 0; k0 < 512; k0 += 16) {
        float4 ra = *(const float4*)&P[(size_t)(k0 + kk0) * 512 + row0 + g * 4];
        float4 rb = *(const float4*)&Q[(size_t)(k0 + kk0) * 512 + col0 + g * 4];
        As[kk0][g*4+0] = ra.x; As[kk0][g*4+1] = ra.y;
        As[kk0][g*4+2] = ra.z; As[kk0][g*4+3] = ra.w;
        Bs[kk0][g*4+0] = rb.x; Bs[kk0][g*4+1] = rb.y;
        Bs[kk0][g*4+2] = rb.z; Bs[kk0][g*4+3] = rb.w;
        __syncthreads();
#pragma unroll
        for (int kk = 0; kk < 16; kk++) {
            ull b0 = *(const ull*)&Bs[kk][tx*4];
            ull b1 = *(const ull*)&Bs[kk][tx*4+2];
            float4 a = *(const float4*)&As[kk][ty*4];
            ull a0=pack2(a.x,a.x), a1=pack2(a.y,a.y);
            ull a2=pack2(a.z,a.z), a3=pack2(a.w,a.w);
            FMA2(acc[0][0],a0,b0); FMA2(acc[0][1],a0,b1);
            FMA2(acc[1][0],a1,b0); FMA2(acc[1][1],a1,b1);
            FMA2(acc[2][0],a2,b0); FMA2(acc[2][1],a2,b1);
            FMA2(acc[3][0],a3,b0); FMA2(acc[3][1],a3,b1);
        }
        __syncthreads();
    }
#pragma unroll
    for (int i = 0; i < 4; i++) {
        int gm = row0 + ty * 4 + i;
#pragma unroll
        for (int j = 0; j < 2; j++) {
            float lo, hi;
            unpack2(acc[i][j], lo, hi);
            int c = col0 + tx * 4 + j * 2;
            out[(size_t)gm * 512 + c]     = lo;
            out[(size_t)gm * 512 + c + 1] = hi;
        }
    }
}

__global__ void k_wc(const float* __restrict__ Wq, const float* __restrict__ bq,
                     const float* __restrict__ Wk, const float* __restrict__ bk) {
    __shared__ float red[256];
    int t = threadIdx.x;
    int i = blockIdx.x * 256 + t;
    float acc = 0.f;
    for (int n = 0; n < EE; n++)
        acc += Wq[(size_t)n * EE + i] * bk[n] + Wk[(size_t)n * EE + i] * bq[n];
    g_wvec[i] = acc;
    if (blockIdx.x == 0) {
        float p = 0.f;
        for (int n = t; n < EE; n += 256) p += bq[n] * bk[n];
        red[t] = p; __syncthreads();
        for (int s = 128; s > 0; s >>= 1) { if (t < s) red[t] += red[t + s]; __syncthreads(); }
        if (t == 0) g_c0[0] = red[0];
    }
}

__global__ void k_h1emb(const float* __restrict__ b_hh) {
    int tk = blockIdx.x;
    const float* gi = &GI_emb[(size_t)tk * G3];
    for (int e = threadIdx.x; e < EE; e += blockDim.x) {
        float r = sigmf(gi[e] + b_hh[e]);
        float z = sigmf(gi[EE + e] + b_hh[EE + e]);
        float n = tanhf(gi[2 * EE + e] + r * b_hh[2 * EE + e]);
        H1_emb[(size_t)tk * EE + e] = (1.f - z) * n;
    }
}

__global__ void k_cinit(const float* __restrict__ bq) {
    int r = blockIdx.x * 8 + (threadIdx.x >> 5);
    int lane = threadIdx.x & 31;
    if (r >= RR) return;
    float s = 0.f;
    for (int e = lane; e < EE; e += 32) s += bq[e] * g_Krel[(size_t)r * EE + e];
#pragma unroll
    for (int off = 16; off > 0; off >>= 1) s += __shfl_down_sync(0xffffffffu, s, off);
    if (lane == 0) g_cs[r] = NSCALE * s;
}

// =================== round-phase kernels ===================

__device__ __forceinline__ float pair_elem(const float* gi, const float* gh,
                                           const float* h1, int e) {
    float r = sigmf(gi[e] + gh[e]);
    float z = sigmf(gi[EE + e] + gh[EE + e]);
    float n = tanhf(gi[2 * EE + e] + r * gh[2 * EE + e]);
    return (1.f - z) * n + z * h1[e];
}

__global__ void k_pairsel(const float* __restrict__ wfc, const float* __restrict__ bfc,
                          const float* __restrict__ b_hh,
                          int npairs, int zloss, float* __restrict__ loss_out, int first) {
    int b = blockIdx.x, t = threadIdx.x;
    int w = t >> 5, lane = t & 31;
    __shared__ int sord[SS];
    __shared__ float sps[SS];
    __shared__ int sbestj;

    // finalize previous round's ghh partials into g_ghh[b][prev_dslot]
    if (!first) {
        int slot = g_dslot[b];
        float* orow = &g_ghh[((size_t)b * SS + slot) * G3];
        const float* gA = &g_gh[0][(size_t)b * G3];
        const float* gB = &g_gh[1][(size_t)b * G3];
        const float* gC = &g_gh[2][(size_t)b * G3];
        const float* gD = &g_gh[3][(size_t)b * G3];
        for (int e = t; e < G3; e += 256)
            orow[e] = gA[e] + gB[e] + gC[e] + gD[e] + b_hh[e];
        __syncthreads();
    }

    if (t < SS) {
        sord[t] = g_ord[b * SS + t];
        sps[t]  = g_pscore[b * SS + t];
    }
    int prev_sel = g_sel[b];
    __syncthreads();

    int j0 = -1, j1 = -1;
    if (first) {
        j0 = w;  j1 = w + 8;
        if (j0 >= npairs) j0 = -1;
        if (j1 >= npairs) j1 = -1;
    } else {
        int cnt = 0, jj[2];
        if (prev_sel - 1 >= 0 && prev_sel - 1 < npairs) jj[cnt++] = prev_sel - 1;
        if (prev_sel >= 0 && prev_sel < npairs)         jj[cnt++] = prev_sel;
        if (w < cnt) j0 = jj[w];
    }
#pragma unroll
    for (int rep = 0; rep < 2; rep++) {
        int j = (rep == 0) ? j0 : j1;
        if (j >= 0) {
            const float* gi = p_gi(b, sord[j + 1]);
            const float* gh = p_ghh(b, sord[j]);
            const float* h1 = p_h1(b, sord[j]);
            float s = 0.f;
            for (int e = lane; e < EE; e += 32)
                s += pair_elem(gi, gh, h1, e) * wfc[e];
#pragma unroll
            for (int off = 16; off > 0; off >>= 1)
                s += __shfl_down_sync(0xffffffffu, s, off);
            if (lane == 0) {
                float sc = sigmf(s + bfc[0]);
                sps[j] = sc;
                g_pscore[b * SS + j] = sc;
            }
        }
    }
    __syncthreads();

    if (t == 0) {
        int bj = 0; float bs = sps[0];
        for (int j = 1; j < npairs; j++)
            if (sps[j] > bs) { bs = sps[j]; bj = j; }
        sbestj = bj;
        g_sel[b] = bj;
        if (zloss >= 0) loss_out[b * SS + zloss] = 0.f;
    }
    __syncthreads();
    int j = sbestj;
    const float* gi = p_gi(b, sord[j + 1]);
    const float* gh = p_ghh(b, sord[j]);
    const float* h1 = p_h1(b, sord[j]);
    for (int e = t; e < EE; e += 256)
        g_pair[(size_t)b * EE + e] = pair_elem(gi, gh, h1, e);
}

__device__ __forceinline__ float bsum(float v, float* red, int t) {
    red[t] = v; __syncthreads();
    for (int s = 128; s > 0; s >>= 1) { if (t < s) red[t] += red[t + s]; __syncthreads(); }
    return red[0];
}
__device__ __forceinline__ float bmax(float v, float* red, int t) {
    red[t] = v; __syncthreads();
    for (int s = 128; s > 0; s >>= 1) { if (t < s) red[t] = fmaxf(red[t], red[t + s]); __syncthreads(); }
    return red[0];
}

__global__ void k_softmax(int lossidx, int L, int do_book,
                          float* __restrict__ loss_out, float* __restrict__ scores_out) {
    int b = blockIdx.x, t = threadIdx.x;
    __shared__ float red[256];
    const float* pp  = &g_pair[(size_t)b * EE];
    const float* tv0 = &g_tv0[(size_t)b * EE];
    const float* tv1 = &g_tv1[(size_t)b * EE];
    const float* s0  = &g_sc0[(size_t)b * RR];
    const float* s1  = &g_sc1[(size_t)b * RR];

    float part = 0.f;
    for (int e = t; e < EE; e += 256)
        part += (tv0[e] + tv1[e] + g_wvec[e]) * pp[e];
    float c1000 = (bsum(part, red, t) + g_c0[0]) * NSCALE;
    __syncthreads();

    float m = -3.4e38f;
    for (int k = t; k <= RR; k += 256) {
        float v = (k < RR) ? ((s0[k] + s1[k]) * NSCALE + g_cs[k]) : c1000;
        m = fmaxf(m, v);
    }
    m = bmax(m, red, t);
    __syncthreads();

    float se = 0.f, sv = 0.f;
    for (int k = t; k <= RR; k += 256) {
        float raw = (k < RR) ? ((s0[k] + s1[k]) * NSCALE + g_cs[k]) : c1000;
        float v = raw - m;
        float ev = expf(v);
        se += ev; sv += ev * v;
    }
    float Z = bsum(se, red, t);
    __syncthreads();
    float S2 = bsum(sv, red, t);
    if (t == 0) {
        loss_out[b * SS + lossidx] = logf(Z) - S2 / Z;
        g_pp[b] = expf(c1000 - m) / Z;
    }

    float* pr = &g_probp[(size_t)b * 1024];
    for (int k = t; k < 1024; k += 256) {
        if (k < RR) {
            float raw = (s0[k] + s1[k]) * NSCALE + g_cs[k];
            pr[k] = expf(raw - m) / Z;
        } else {
            pr[k] = 0.f;
        }
    }
    if (scores_out) {
        for (int k = t; k <= RR; k += 256) {
            float raw = (k < RR) ? ((s0[k] + s1[k]) * NSCALE + g_cs[k]) : c1000;
            scores_out[(size_t)b * (RR + 1) + k] = raw;
        }
    }
    if (t == 0 && do_book) {
        int sel = g_sel[b];
        int* ord = &g_ord[b * SS];
        float* ps = &g_pscore[b * SS];
        int slot = ord[sel];
        g_dslot[b] = slot;
        g_src[b * SS + slot] = -1;
        for (int i = sel + 1; i < L - 1; i++) { ord[i] = ord[i + 1]; ps[i] = ps[i + 1]; }
    }
}

// finalize gi (sum 4 gimix partials + pp*(giP partials + b_ih)), scatter, compute h1
__global__ void k_h1fin(const float* __restrict__ b_ih, const float* __restrict__ b_hh) {
    __shared__ __align__(16) float sgi[G3];
    int b = blockIdx.x, t = threadIdx.x;
    int slot = g_dslot[b];
    float pp = g_pp[b];
    float* orow = &g_gi[((size_t)b * SS + slot) * G3];
    const float* m0 = &g_gm4[0][(size_t)b * G3];
    const float* m1 = &g_gm4[1][(size_t)b * G3];
    const float* m2 = &g_gm4[2][(size_t)b * G3];
    const float* m3 = &g_gm4[3][(size_t)b * G3];
    const float* p0 = &g_gp0[(size_t)b * G3];
    const float* p1 = &g_gp1[(size_t)b * G3];
    for (int e = t; e < G3; e += 256) {
        float v = m0[e] + m1[e] + m2[e] + m3[e] + pp * (p0[e] + p1[e] + b_ih[e]);
        sgi[e] = v;
        orow[e] = v;
    }
    __syncthreads();
    for (int e = t; e < EE; e += 256) {
        float r = sigmf(sgi[e] + b_hh[e]);
        float z = sigmf(sgi[EE + e] + b_hh[EE + e]);
        float n = tanhf(sgi[2 * EE + e] + r * b_hh[2 * EE + e]);
        float h = (1.f - z) * n;
        g_h1[((size_t)b * SS + slot) * EE + e] = h;
        g_newh1[(size_t)b * EE + e] = h;
    }
}

// ---------------- host ----------------
extern "C" void kernel_launch(void* const* d_in, const int* in_sizes, int n_in,
                              void* d_out, int out_size) {
    const int*   tokens = (const int*)  d_in[0];
    const float* emb    = (const float*)d_in[1];
    const float* W_ih   = (const float*)d_in[2];
    const float* W_hh   = (const float*)d_in[3];
    const float* b_ih   = (const float*)d_in[4];
    const float* b_hh   = (const float*)d_in[5];
    const float* w_fc   = (const float*)d_in[6];
    const float* b_fc   = (const float*)d_in[7];
    const float* Wq     = (const float*)d_in[8];
    const float* bq     = (const float*)d_in[9];
    const float* Wk     = (const float*)d_in[10];
    const float* bk     = (const float*)d_in[11];

    float* out_scores = (float*)d_out;                         // 128 x 1001
    float* out_loss   = (float*)d_out + (size_t)BB * (RR + 1); // 128 x 16

    float *GI, *H1, *GHH, *Krel, *KW, *AT;
    cudaGetSymbolAddress((void**)&GI, GI_emb);
    cudaGetSymbolAddress((void**)&H1, H1_emb);
    cudaGetSymbolAddress((void**)&GHH, GHH_emb);
    cudaGetSymbolAddress((void**)&Krel, g_Krel);
    cudaGetSymbolAddress((void**)&KW, g_KW);
    cudaGetSymbolAddress((void**)&AT, g_AT);

    // ---- init (once per call) ----
    k_init<<<BB, 32>>>(tokens);
    k_tab<<<dim3(24, 16), 256>>>(emb, W_ih, b_ih, GI, RR, G3, G3, 1.f);
    k_h1emb<<<RR, 256>>>(b_hh);
    k_tab<<<dim3(24, 16), 256>>>(H1, W_hh, b_hh, GHH, RR, G3, G3, 1.f);
    k_tab<<<dim3(8, 16), 256>>>(emb, Wk, bk, Krel, RR, EE, EE, 1.f);
    k_gemm_kn<<<dim3(8, 16), 256>>>(Krel, Wq, KW, RR, EE, EE);
    k_cinit<<<125, 256>>>(bq);
    k_gemm_tn<<<dim3(8, 8), 256>>>(Wk, Wq, AT);
    k_wc<<<2, 256>>>(Wq, bq, Wk, bk);

    // ---- 14 merge rounds ----
    for (int i = 0; i < 14; i++) {
        int L = SS - i;
        k_pairsel<<<BB, 256>>>(w_fc, b_fc, b_hh, L - 1, -1, out_loss, i == 0);
        k_mm<<<dim3(24, 2, 2), 256>>>(PH_BGA, W_ih, W_hh);   // scores + tvec
        k_softmax<<<BB, 256>>>(i, L, 1, out_loss, NULL);
        k_mm<<<dim3(24, 2, 6), 256>>>(PH_GIMIX, W_ih, W_hh); // gimix slices + giP
        k_h1fin<<<BB, 256>>>(b_ih, b_hh);
        k_mm<<<dim3(24, 2, 4), 256>>>(PH_GHH, W_ih, W_hh);   // newh1 @ W_hh partials
    }
    // ---- final round (L=2) + output attention ----
    k_pairsel<<<BB, 256>>>(w_fc, b_fc, b_hh, 1, 14, out_loss, 0);
    k_mm<<<dim3(24, 2, 2), 256>>>(PH_BGA, W_ih, W_hh);       // scores + tvec only
    k_softmax<<<BB, 256>>>(15, 0, 0, out_loss, out_scores);
}